// round 2
// baseline (speedup 1.0000x reference)
#include <cuda_runtime.h>
#include <cstddef>

// Problem constants (fixed by the reference)
#define Bq 4
#define Lq 128
#define Dq 128
#define Hq 8
#define Vq 32000
#define DHq (Dq*Hq)          // 1024
#define NEGC 1e9f
#define NROWS (Bq*Lq)        // 512
#define NSPLIT 50
#define VCHUNK (Vq/NSPLIT)   // 640

// ---------------- scratch (device globals; no allocation) ----------------
__device__ float g_meanE_part[128*128];
__device__ float g_meanE[Dq];
__device__ float g_Tp[2*DHq*Dq];                 // Tp[k][(a*H+c)][b]
__device__ float g_qz[NROWS*Dq];
__device__ float g_zlog[NROWS*Dq];
__device__ float g_G[NROWS*Dq];
__device__ float g_U[NROWS*Dq];
__device__ float g_t1[Bq*2*Lq*DHq];              // [z][k][i][(b*H+c)]
__device__ float g_F[Bq*2*Hq*Lq*Lq];             // [z][k][c][i][j]
__device__ float g_Hm[2*Bq*Hq*Lq*Lq];            // [k][z][c][i][j]
__device__ float g_s1[Bq*2*Lq*DHq];              // [z][k][i][(b*H+c)]
__device__ float g_s2[Bq*2*Lq*DHq];              // [z][k][j][(a*H+c)]
__device__ float g_qx[(size_t)NROWS*Vq];
__device__ float g_rmax[NROWS];
__device__ float g_rsum[NROWS];
__device__ float g_Cpart[(size_t)NSPLIT*NROWS*Dq];

// ---------------- small kernels ----------------

__global__ void k_meanE_part(const float* __restrict__ E){
    int b = blockIdx.x, t = threadIdx.x;
    float s = 0.f;
    int v0 = b * (Vq/128);
    for (int v = 0; v < Vq/128; v++) s += E[(size_t)(v0+v)*Dq + t];
    g_meanE_part[b*128 + t] = s;
}
__global__ void k_meanE_red(){
    int t = threadIdx.x;
    float s = 0.f;
    for (int b = 0; b < 128; b++) s += g_meanE_part[b*128 + t];
    g_meanE[t] = s / (float)Vq;
}

__global__ void k_permT(const float* __restrict__ T){
    int idx = blockIdx.x*256 + threadIdx.x;   // over 2*D*D*H
    if (idx >= 2*Dq*Dq*Hq) return;
    int c = idx % Hq;
    int b = (idx/Hq) % Dq;
    int a = (idx/(Hq*Dq)) % Dq;
    int k = idx/(Hq*Dq*Dq);
    g_Tp[((size_t)k*DHq + a*Hq + c)*Dq + b] = T[idx];
}

__global__ void k_compose_init(const float* __restrict__ x, const int* __restrict__ m_mask){
    int idx = blockIdx.x*256 + threadIdx.x;   // B*L*D
    int d = idx % Dq, row = idx / Dq;
    float mm = (float)m_mask[row];
    g_zlog[idx] = x[idx]*(1.f-mm) + g_meanE[d]*mm;
}

__global__ void k_compose_ueff(const float* __restrict__ x, const int* __restrict__ m_mask, int mode){
    int idx = blockIdx.x*256 + threadIdx.x;
    int d = idx % Dq, row = idx / Dq;
    float mm = (float)m_mask[row];
    float u = mode ? g_U[idx] : g_meanE[d];
    g_zlog[idx] = x[idx]*(1.f-mm) + u*mm + g_G[idx];
}

__global__ void k_softmax128(const int* __restrict__ mask){
    int row = blockIdx.x, t = threadIdx.x;
    float v = g_zlog[row*Dq + t];
    __shared__ float r1[4], r2[4];
    float m = v;
    #pragma unroll
    for (int o = 16; o; o >>= 1) m = fmaxf(m, __shfl_xor_sync(0xffffffffu, m, o));
    if ((t&31)==0) r1[t>>5] = m;
    __syncthreads();
    m = fmaxf(fmaxf(r1[0],r1[1]), fmaxf(r1[2],r1[3]));
    float e = __expf(v - m);
    float s = e;
    #pragma unroll
    for (int o = 16; o; o >>= 1) s += __shfl_xor_sync(0xffffffffu, s, o);
    if ((t&31)==0) r2[t>>5] = s;
    __syncthreads();
    s = r2[0]+r2[1]+r2[2]+r2[3];
    float keep = (mask[row] != 0) ? 1.f : 0.f;
    g_qz[row*Dq + t] = e/s*keep;
}

// build q_h row, softmax over j, emit triangle-masked H0/H1
__global__ void k_hsoftmax(const int* __restrict__ mask){
    int bi = blockIdx.x;                    // z*H*L + c*L + i
    int i = bi & (Lq-1);
    int c = (bi >> 7) & (Hq-1);
    int z = bi >> 10;
    int j = threadIdx.x;
    bool mok = (mask[z*Lq+i] != 0) && (mask[z*Lq+j] != 0);
    float v;
    if (!mok || j == i) v = -NEGC;
    else if (j > i) v = g_F[((((size_t)z*2+0)*Hq+c)*Lq+i)*Lq + j];
    else            v = g_F[((((size_t)z*2+1)*Hq+c)*Lq+i)*Lq + j];
    __shared__ float r1[4], r2[4];
    float m = v;
    #pragma unroll
    for (int o = 16; o; o >>= 1) m = fmaxf(m, __shfl_xor_sync(0xffffffffu, m, o));
    if ((j&31)==0) r1[j>>5] = m;
    __syncthreads();
    m = fmaxf(fmaxf(r1[0],r1[1]), fmaxf(r1[2],r1[3]));
    float e = __expf(v - m);
    float s = e;
    #pragma unroll
    for (int o = 16; o; o >>= 1) s += __shfl_xor_sync(0xffffffffu, s, o);
    if ((j&31)==0) r2[j>>5] = s;
    __syncthreads();
    s = r2[0]+r2[1]+r2[2]+r2[3];
    float p = e/s;
    size_t o0 = ((((size_t)0*Bq+z)*Hq+c)*Lq+i)*Lq + j;
    size_t o1 = ((((size_t)1*Bq+z)*Hq+c)*Lq+i)*Lq + j;
    g_Hm[o0] = (j > i) ? p : 0.f;
    g_Hm[o1] = (j < i) ? p : 0.f;
}

// per-row max & sum(exp) over V
__global__ void k_rowstat(){
    int row = blockIdx.x, t = threadIdx.x;
    const float* p = &g_qx[(size_t)row*Vq];
    __shared__ float rm[8], rs[8];
    float m = -3.4e38f;
    for (int v = t; v < Vq; v += 256) m = fmaxf(m, p[v]);
    #pragma unroll
    for (int o = 16; o; o >>= 1) m = fmaxf(m, __shfl_xor_sync(0xffffffffu, m, o));
    if ((t&31)==0) rm[t>>5] = m;
    __syncthreads();
    float mg = rm[0];
    #pragma unroll
    for (int w = 1; w < 8; w++) mg = fmaxf(mg, rm[w]);
    float s = 0.f;
    for (int v = t; v < Vq; v += 256) s += __expf(p[v] - mg);
    #pragma unroll
    for (int o = 16; o; o >>= 1) s += __shfl_xor_sync(0xffffffffu, s, o);
    if ((t&31)==0) rs[t>>5] = s;
    __syncthreads();
    if (t == 0){
        float ss = 0.f;
        for (int w = 0; w < 8; w++) ss += rs[w];
        g_rmax[row] = mg; g_rsum[row] = ss;
    }
}

// split-K: Cpart[sp][rows 32][128] = sum_{v in chunk} exp(qx-rmax) * E
__global__ void __launch_bounds__(256) k_softexp(const float* __restrict__ E){
    int rb = blockIdx.x, sp = blockIdx.y, tid = threadIdx.x;
    __shared__ float As[32][33];
    __shared__ float Bs[32][128];
    float acc[4][4] = {};
    int r0 = rb*32;
    int tr = tid >> 5;   // 0..7  (rows tr*4..tr*4+3)
    int tc = tid & 31;   // 0..31 (cols tc*4..tc*4+3)
    int v0 = sp*VCHUNK;
    for (int vs = 0; vs < VCHUNK; vs += 32){
        #pragma unroll
        for (int p_ = 0; p_ < 4; p_++){
            int idx = tid + p_*256;
            int r = idx >> 5, vv = idx & 31;
            float q = g_qx[(size_t)(r0+r)*Vq + v0 + vs + vv];
            As[r][vv] = __expf(q - g_rmax[r0+r]);
        }
        #pragma unroll
        for (int p_ = 0; p_ < 4; p_++){
            int idx4 = tid + p_*256;
            int vv = idx4 >> 5, c4 = idx4 & 31;
            *(float4*)&Bs[vv][c4*4] = *(const float4*)&E[(size_t)(v0+vs+vv)*Dq + c4*4];
        }
        __syncthreads();
        #pragma unroll
        for (int k = 0; k < 32; k++){
            float a0 = As[tr*4+0][k], a1 = As[tr*4+1][k];
            float a2 = As[tr*4+2][k], a3 = As[tr*4+3][k];
            float4 b = *(float4*)&Bs[k][tc*4];
            acc[0][0] += a0*b.x; acc[0][1] += a0*b.y; acc[0][2] += a0*b.z; acc[0][3] += a0*b.w;
            acc[1][0] += a1*b.x; acc[1][1] += a1*b.y; acc[1][2] += a1*b.z; acc[1][3] += a1*b.w;
            acc[2][0] += a2*b.x; acc[2][1] += a2*b.y; acc[2][2] += a2*b.z; acc[2][3] += a2*b.w;
            acc[3][0] += a3*b.x; acc[3][1] += a3*b.y; acc[3][2] += a3*b.z; acc[3][3] += a3*b.w;
        }
        __syncthreads();
    }
    float* out = &g_Cpart[((size_t)sp*NROWS + r0)*Dq];
    #pragma unroll
    for (int r = 0; r < 4; r++)
        *(float4*)&out[(tr*4+r)*Dq + tc*4] = make_float4(acc[r][0],acc[r][1],acc[r][2],acc[r][3]);
}

__global__ void k_reduce_split(){
    int idx = blockIdx.x*256 + threadIdx.x;   // NROWS*D
    int row = idx / Dq;
    float s = 0.f;
    for (int sp = 0; sp < NSPLIT; sp++) s += g_Cpart[(size_t)sp*NROWS*Dq + idx];
    g_U[idx] = s / g_rsum[row];
}

// C[i,v] = sum_a qz[i,a] * E[v,a];  128x128 tile, 8x8 microtile
__global__ void __launch_bounds__(256) k_qx_gemm(const float* __restrict__ E, float* __restrict__ C){
    int vb = blockIdx.x, rb = blockIdx.y, tid = threadIdx.x;
    int tx = tid & 15, ty = tid >> 4;
    __shared__ float As[8][128];
    __shared__ float Bs[8][128];
    float acc[8][8] = {};
    const float* A  = &g_qz[rb*128*Dq];
    const float* Bm = &E[(size_t)vb*128*Dq];
    int lr = tid >> 1, lk = (tid & 1)*4;
    for (int k0 = 0; k0 < Dq; k0 += 8){
        float4 av = *(const float4*)&A [lr*Dq + k0 + lk];
        float4 bv = *(const float4*)&Bm[(size_t)lr*Dq + k0 + lk];
        As[lk+0][lr]=av.x; As[lk+1][lr]=av.y; As[lk+2][lr]=av.z; As[lk+3][lr]=av.w;
        Bs[lk+0][lr]=bv.x; Bs[lk+1][lr]=bv.y; Bs[lk+2][lr]=bv.z; Bs[lk+3][lr]=bv.w;
        __syncthreads();
        #pragma unroll
        for (int k = 0; k < 8; k++){
            float4 a0 = *(float4*)&As[k][ty*8],   a1 = *(float4*)&As[k][ty*8+4];
            float4 b0 = *(float4*)&Bs[k][tx*8],   b1 = *(float4*)&Bs[k][tx*8+4];
            float a[8] = {a0.x,a0.y,a0.z,a0.w,a1.x,a1.y,a1.z,a1.w};
            float b[8] = {b0.x,b0.y,b0.z,b0.w,b1.x,b1.y,b1.z,b1.w};
            #pragma unroll
            for (int r = 0; r < 8; r++)
                #pragma unroll
                for (int c = 0; c < 8; c++) acc[r][c] += a[r]*b[c];
        }
        __syncthreads();
    }
    #pragma unroll
    for (int r = 0; r < 8; r++){
        float* o = &C[(size_t)(rb*128 + ty*8 + r)*Vq + vb*128 + tx*8];
        *(float4*)&o[0] = make_float4(acc[r][0],acc[r][1],acc[r][2],acc[r][3]);
        *(float4*)&o[4] = make_float4(acc[r][4],acc[r][5],acc[r][6],acc[r][7]);
    }
}

// Generic strided batched GEMM: C[i,j] (+)= sum_k A[i,k]*B[k,j]
// batch index bz -> (i1,i2,i3): i3=bz%b3, i2=(bz/b3)%b2, i1=bz/(b3*b2)
__global__ void __launch_bounds__(256) k_gemm_gen(
    const float* __restrict__ A, const float* __restrict__ Bm, float* __restrict__ C,
    int K,
    int sAi, int sAk, int sBk, int sBj, int sCi, int sCj,
    int b3, int b2,
    int aB1, int aB2, int aB3,
    int bB1, int bB2, int bB3,
    int cB1, int cB2, int cB3,
    int accumulate)
{
    int bz = blockIdx.z;
    int i3 = bz % b3; int t_ = bz / b3; int i2 = t_ % b2; int i1 = t_ / b2;
    A  += (size_t)i1*aB1 + (size_t)i2*aB2 + (size_t)i3*aB3;
    Bm += (size_t)i1*bB1 + (size_t)i2*bB2 + (size_t)i3*bB3;
    C  += (size_t)i1*cB1 + (size_t)i2*cB2 + (size_t)i3*cB3;
    int m0 = blockIdx.y*64, n0 = blockIdx.x*64;
    __shared__ float As[16][64], Bs[16][64];
    int tid = threadIdx.x, tx = tid & 15, ty = tid >> 4;
    float acc[4][4] = {};
    for (int k0 = 0; k0 < K; k0 += 16){
        #pragma unroll
        for (int p_ = 0; p_ < 4; p_++){
            int idx = tid + p_*256;
            int rc = idx & 63, kk = idx >> 6;
            As[kk][rc] = A [(size_t)(m0+rc)*sAi + (size_t)(k0+kk)*sAk];
            Bs[kk][rc] = Bm[(size_t)(k0+kk)*sBk + (size_t)(n0+rc)*sBj];
        }
        __syncthreads();
        #pragma unroll
        for (int kk = 0; kk < 16; kk++){
            float4 a = *(float4*)&As[kk][ty*4];
            float4 b = *(float4*)&Bs[kk][tx*4];
            float av[4] = {a.x,a.y,a.z,a.w};
            float bv[4] = {b.x,b.y,b.z,b.w};
            #pragma unroll
            for (int r = 0; r < 4; r++)
                #pragma unroll
                for (int c = 0; c < 4; c++) acc[r][c] += av[r]*bv[c];
        }
        __syncthreads();
    }
    #pragma unroll
    for (int r = 0; r < 4; r++)
        #pragma unroll
        for (int c = 0; c < 4; c++){
            float* p = &C[(size_t)(m0+ty*4+r)*sCi + (size_t)(n0+tx*4+c)*sCj];
            if (accumulate) *p += acc[r][c]; else *p = acc[r][c];
        }
}

// ---------------- host ----------------

extern "C" void kernel_launch(void* const* d_in, const int* in_sizes, int n_in,
                              void* d_out, int out_size){
    const float* x      = (const float*)d_in[0];
    const int*   mask   = (const int*)  d_in[1];
    const float* E      = (const float*)d_in[2];
    const int*   m_mask = (const int*)  d_in[3];
    const float* T      = (const float*)d_in[4];
    float* out = (float*)d_out;

    void* q;
    float *Pqz,*Pt1,*PF,*PHm,*Ps1,*Ps2,*PG,*PTp,*Pqx;
    cudaGetSymbolAddress(&q, g_qz);  Pqz  = (float*)q;
    cudaGetSymbolAddress(&q, g_t1);  Pt1  = (float*)q;
    cudaGetSymbolAddress(&q, g_F);   PF   = (float*)q;
    cudaGetSymbolAddress(&q, g_Hm);  PHm  = (float*)q;
    cudaGetSymbolAddress(&q, g_s1);  Ps1  = (float*)q;
    cudaGetSymbolAddress(&q, g_s2);  Ps2  = (float*)q;
    cudaGetSymbolAddress(&q, g_G);   PG   = (float*)q;
    cudaGetSymbolAddress(&q, g_Tp);  PTp  = (float*)q;
    cudaGetSymbolAddress(&q, g_qx);  Pqx  = (float*)q;

    // preprocessing
    k_meanE_part<<<128,128>>>(E);
    k_meanE_red<<<1,128>>>();
    k_permT<<<(2*Dq*Dq*Hq + 255)/256, 256>>>(T);
    k_compose_init<<<NROWS*Dq/256, 256>>>(x, m_mask);
    k_softmax128<<<NROWS, 128>>>(mask);

    for (int t = 0; t < 4; t++){
        // t1[z,k,i,(b,c)] = sum_a qz[z,i,a] T[k,a,(b,c)]   M=128 N=1024 K=128
        k_gemm_gen<<<dim3(16,2,8), 256>>>(Pqz, T, Pt1, 128,
            Dq,1,  DHq,1,  DHq,1,
            1,2,
            Lq*Dq,0,0,   0,Dq*DHq,0,   2*Lq*DHq,Lq*DHq,0,  0);

        // F[z,k,c,i,j] = sum_b t1[z,k,i,(b,c)] qz[z,j,b]   M=N=K=128
        k_gemm_gen<<<dim3(2,2,64), 256>>>(Pt1, Pqz, PF, 128,
            DHq,Hq,  1,Dq,  Lq,1,
            8,2,
            2*Lq*DHq,Lq*DHq,1,  Lq*Dq,0,0,  2*Hq*Lq*Lq,Hq*Lq*Lq,Lq*Lq,  0);

        k_hsoftmax<<<Bq*Hq*Lq, 128>>>(mask);

        // s1[z,k,i,(b,c)] = sum_j Hm[k,z,c,i,j] qz[z,j,b]
        k_gemm_gen<<<dim3(2,2,64), 256>>>(PHm, Pqz, Ps1, 128,
            Lq,1,  Dq,1,  DHq,Hq,
            8,2,
            Hq*Lq*Lq, Bq*Hq*Lq*Lq, Lq*Lq,   Lq*Dq,0,0,   2*Lq*DHq,Lq*DHq,1,  0);

        // s2[z,k,j,(a,c)] = sum_i Hm[k,z,c,i,j] qz[z,i,a]
        k_gemm_gen<<<dim3(2,2,64), 256>>>(PHm, Pqz, Ps2, 128,
            1,Lq,  Dq,1,  DHq,Hq,
            8,2,
            Hq*Lq*Lq, Bq*Hq*Lq*Lq, Lq*Lq,   Lq*Dq,0,0,   2*Lq*DHq,Lq*DHq,1,  0);

        // G[z,i,a]  = sum_{k,(b,c)} s1[z,k,i,m] T[k,a,m]       K=1024
        for (int k = 0; k < 2; k++)
            k_gemm_gen<<<dim3(2,2,4), 256>>>(Ps1 + (size_t)k*Lq*DHq, T + (size_t)k*Dq*DHq, PG, DHq,
                DHq,1,  1,DHq,  Dq,1,
                1,1,
                2*Lq*DHq,0,0,   0,0,0,   Lq*Dq,0,0,   (k==0)?0:1);

        // G[z,j,b] += sum_{k,(a,c)} s2[z,k,j,m] Tp[k,m,b]      K=1024
        for (int k = 0; k < 2; k++)
            k_gemm_gen<<<dim3(2,2,4), 256>>>(Ps2 + (size_t)k*Lq*DHq, PTp + (size_t)k*DHq*Dq, PG, DHq,
                DHq,1,  Dq,1,  Dq,1,
                1,1,
                2*Lq*DHq,0,0,   0,0,0,   Lq*Dq,0,0,   1);

        if (t == 0){
            k_compose_ueff<<<NROWS*Dq/256, 256>>>(x, m_mask, 0);
        } else {
            k_rowstat<<<NROWS, 256>>>();
            k_softexp<<<dim3(16, NSPLIT), 256>>>(E);
            k_reduce_split<<<NROWS*Dq/256, 256>>>();
            k_compose_ueff<<<NROWS*Dq/256, 256>>>(x, m_mask, 1);
        }
        k_softmax128<<<NROWS, 128>>>(mask);

        // q_x = qz @ E^T  -> scratch (t<3) or output (t==3)
        k_qx_gemm<<<dim3(Vq/128, 4), 256>>>(E, (t == 3) ? out : Pqx);
    }
}

// round 3
// speedup vs baseline: 1.3797x; 1.3797x over previous
#include <cuda_runtime.h>
#include <cstdint>
#include <cstddef>

// Problem constants
#define Bq 4
#define Lq 128
#define Dq 128
#define Hq 8
#define Vq 32000
#define DHq (Dq*Hq)          // 1024
#define NEGC 1e9f
#define NROWS (Bq*Lq)        // 512
#define NSPLIT 50
#define VCHUNK (Vq/NSPLIT)   // 640

// ---------------- scratch (device globals) ----------------
__device__ float g_meanE_part[128*128];
__device__ float g_meanE[Dq];
__device__ float g_Tp[2*DHq*Dq];                 // Tp[k][(a*H+c)][b]
__device__ float g_qz[NROWS*Dq];
__device__ float g_zlog[NROWS*Dq];
__device__ float g_G[NROWS*Dq];
__device__ float g_U[NROWS*Dq];
__device__ float g_t1[Bq*2*Lq*DHq];              // [z][k][i][(b*H+c)]
__device__ float g_F[Bq*2*Hq*Lq*Lq];             // [z][k][c][i][j]
__device__ float g_Hm[2*Bq*Hq*Lq*Lq];            // [k][z][c][i][j]
__device__ float g_s1[Bq*2*Lq*DHq];
__device__ float g_s2[Bq*2*Lq*DHq];
__device__ float g_Um[(size_t)NSPLIT*NROWS*Dq];  // flash partial accumulators
__device__ float g_mrow[NSPLIT*NROWS];
__device__ float g_srow[NSPLIT*NROWS];

// ---------------- tf32 mma helpers ----------------
__device__ __forceinline__ uint32_t f2tf(float f){
    uint32_t u; asm("cvt.rna.tf32.f32 %0, %1;" : "=r"(u) : "f"(f)); return u;
}
__device__ __forceinline__ void mma8(float c[4], const uint32_t a[4], const uint32_t b[2]){
    asm("mma.sync.aligned.m16n8k8.row.col.f32.tf32.tf32.f32 "
        "{%0,%1,%2,%3},{%4,%5,%6,%7},{%8,%9},{%0,%1,%2,%3};"
        : "+f"(c[0]),"+f"(c[1]),"+f"(c[2]),"+f"(c[3])
        : "r"(a[0]),"r"(a[1]),"r"(a[2]),"r"(a[3]),"r"(b[0]),"r"(b[1]));
}

// ---------------- small kernels ----------------
__global__ void k_meanE_part(const float* __restrict__ E){
    int b = blockIdx.x, t = threadIdx.x;
    float s = 0.f;
    int v0 = b * (Vq/128);
    for (int v = 0; v < Vq/128; v++) s += E[(size_t)(v0+v)*Dq + t];
    g_meanE_part[b*128 + t] = s;
}
__global__ void k_meanE_red(){
    int t = threadIdx.x;
    float s = 0.f;
    for (int b = 0; b < 128; b++) s += g_meanE_part[b*128 + t];
    g_meanE[t] = s / (float)Vq;
}

__global__ void k_permT(const float* __restrict__ T){
    int idx = blockIdx.x*256 + threadIdx.x;
    if (idx >= 2*Dq*Dq*Hq) return;
    int c = idx % Hq;
    int b = (idx/Hq) % Dq;
    int a = (idx/(Hq*Dq)) % Dq;
    int k = idx/(Hq*Dq*Dq);
    g_Tp[((size_t)k*DHq + a*Hq + c)*Dq + b] = T[idx];
}

__global__ void k_compose_init(const float* __restrict__ x, const int* __restrict__ m_mask){
    int idx = blockIdx.x*256 + threadIdx.x;
    int d = idx % Dq, row = idx / Dq;
    float mm = (float)m_mask[row];
    g_zlog[idx] = x[idx]*(1.f-mm) + g_meanE[d]*mm;
}

__global__ void k_compose_ueff(const float* __restrict__ x, const int* __restrict__ m_mask, int mode){
    int idx = blockIdx.x*256 + threadIdx.x;
    int d = idx % Dq, row = idx / Dq;
    float mm = (float)m_mask[row];
    float u = mode ? g_U[idx] : g_meanE[d];
    g_zlog[idx] = x[idx]*(1.f-mm) + u*mm + g_G[idx];
}

__global__ void k_softmax128(const int* __restrict__ mask){
    int row = blockIdx.x, t = threadIdx.x;
    float v = g_zlog[row*Dq + t];
    __shared__ float r1[4], r2[4];
    float m = v;
    #pragma unroll
    for (int o = 16; o; o >>= 1) m = fmaxf(m, __shfl_xor_sync(0xffffffffu, m, o));
    if ((t&31)==0) r1[t>>5] = m;
    __syncthreads();
    m = fmaxf(fmaxf(r1[0],r1[1]), fmaxf(r1[2],r1[3]));
    float e = __expf(v - m);
    float s = e;
    #pragma unroll
    for (int o = 16; o; o >>= 1) s += __shfl_xor_sync(0xffffffffu, s, o);
    if ((t&31)==0) r2[t>>5] = s;
    __syncthreads();
    s = r2[0]+r2[1]+r2[2]+r2[3];
    float keep = (mask[row] != 0) ? 1.f : 0.f;
    g_qz[row*Dq + t] = e/s*keep;
}

__global__ void k_hsoftmax(const int* __restrict__ mask){
    int bi = blockIdx.x;                    // z*H*L + c*L + i
    int i = bi & (Lq-1);
    int c = (bi >> 7) & (Hq-1);
    int z = bi >> 10;
    int j = threadIdx.x;
    bool mok = (mask[z*Lq+i] != 0) && (mask[z*Lq+j] != 0);
    float v;
    if (!mok || j == i) v = -NEGC;
    else if (j > i) v = g_F[((((size_t)z*2+0)*Hq+c)*Lq+i)*Lq + j];
    else            v = g_F[((((size_t)z*2+1)*Hq+c)*Lq+i)*Lq + j];
    __shared__ float r1[4], r2[4];
    float m = v;
    #pragma unroll
    for (int o = 16; o; o >>= 1) m = fmaxf(m, __shfl_xor_sync(0xffffffffu, m, o));
    if ((j&31)==0) r1[j>>5] = m;
    __syncthreads();
    m = fmaxf(fmaxf(r1[0],r1[1]), fmaxf(r1[2],r1[3]));
    float e = __expf(v - m);
    float s = e;
    #pragma unroll
    for (int o = 16; o; o >>= 1) s += __shfl_xor_sync(0xffffffffu, s, o);
    if ((j&31)==0) r2[j>>5] = s;
    __syncthreads();
    s = r2[0]+r2[1]+r2[2]+r2[3];
    float p = e/s;
    size_t o0 = ((((size_t)0*Bq+z)*Hq+c)*Lq+i)*Lq + j;
    size_t o1 = ((((size_t)1*Bq+z)*Hq+c)*Lq+i)*Lq + j;
    g_Hm[o0] = (j > i) ? p : 0.f;
    g_Hm[o1] = (j < i) ? p : 0.f;
}

// ---------------- fused flash V kernel ----------------
// Computes partial (m, s, U) for U = softmax_v(qz @ E^T) @ E over one V split.
// Block: 64 rows x 640 V (10 chunks of 64). 8 warps: wm=warp&3 (16-row slab),
// wn=warp>>2 (col half). smem padded stride 132 for conflict-free frag loads.
#define QZW (64*132)
#define EW  (64*132)
#define PW  (64*68)
#define FLASH_SMEM ((QZW + EW + PW + 64*3 + 128)*4)

__global__ void __launch_bounds__(256) k_flash(const float* __restrict__ E){
    extern __shared__ uint32_t sh[];
    uint32_t* qz_s = sh;
    uint32_t* E_s  = sh + QZW;
    uint32_t* p_s  = E_s + EW;
    float* runm = (float*)(p_s + PW);
    float* runs = runm + 64;
    float* fsc  = runs + 64;
    float* wred = fsc + 64;            // [2][64]

    int tid = threadIdx.x;
    int sp = blockIdx.x, by = blockIdx.y;
    int warp = tid>>5, lane = tid&31;
    int wm = warp&3, wn = warp>>2;
    int g = lane>>2, q = lane&3;

    // load qz tile -> tf32
    {
        const float* A = &g_qz[(by*64)*Dq];
        #pragma unroll
        for (int it = 0; it < 8; it++){
            int i4 = tid + it*256;
            int r = i4 >> 5, c4 = (i4 & 31)*4;
            float4 v = *(const float4*)&A[r*Dq + c4];
            qz_s[r*132+c4+0]=f2tf(v.x); qz_s[r*132+c4+1]=f2tf(v.y);
            qz_s[r*132+c4+2]=f2tf(v.z); qz_s[r*132+c4+3]=f2tf(v.w);
        }
    }
    if (tid < 64){ runm[tid] = -3.4e38f; runs[tid] = 0.f; }

    float Ua[8][4];
    #pragma unroll
    for (int i = 0; i < 8; i++){ Ua[i][0]=0;Ua[i][1]=0;Ua[i][2]=0;Ua[i][3]=0; }

    int v0 = sp*VCHUNK;
    int rlo = wm*16 + g, rhi = rlo + 8;

    for (int ci = 0; ci < VCHUNK/64; ci++){
        __syncthreads();
        // load E tile (64 x 128) -> tf32
        const float* Eb = &E[(size_t)(v0 + ci*64)*Dq];
        #pragma unroll
        for (int it = 0; it < 8; it++){
            int i4 = tid + it*256;
            int r = i4 >> 5, c4 = (i4 & 31)*4;
            float4 v = *(const float4*)&Eb[r*Dq + c4];
            E_s[r*132+c4+0]=f2tf(v.x); E_s[r*132+c4+1]=f2tf(v.y);
            E_s[r*132+c4+2]=f2tf(v.z); E_s[r*132+c4+3]=f2tf(v.w);
        }
        __syncthreads();

        // MMA1: L[64x64] = qz @ E^T   (warp tile 16x32)
        float L[4][4];
        #pragma unroll
        for (int i = 0; i < 4; i++){ L[i][0]=0;L[i][1]=0;L[i][2]=0;L[i][3]=0; }
        const uint32_t* qrow = &qz_s[rlo*132 + q];
        #pragma unroll
        for (int ks = 0; ks < 16; ks++){
            int kb = ks*8;
            uint32_t a[4];
            a[0] = qrow[kb]; a[1] = qrow[kb + 8*132];
            a[2] = qrow[kb+4]; a[3] = qrow[kb+4 + 8*132];
            #pragma unroll
            for (int nt = 0; nt < 4; nt++){
                int nc = wn*32 + nt*8 + g;
                uint32_t b[2] = { E_s[nc*132 + kb + q], E_s[nc*132 + kb + q + 4] };
                mma8(L[nt], a, b);
            }
        }

        // per-row max of this tile
        float mlo = -3.4e38f, mhi = -3.4e38f;
        #pragma unroll
        for (int nt = 0; nt < 4; nt++){
            mlo = fmaxf(mlo, fmaxf(L[nt][0], L[nt][1]));
            mhi = fmaxf(mhi, fmaxf(L[nt][2], L[nt][3]));
        }
        mlo = fmaxf(mlo, __shfl_xor_sync(0xffffffffu, mlo, 1));
        mlo = fmaxf(mlo, __shfl_xor_sync(0xffffffffu, mlo, 2));
        mhi = fmaxf(mhi, __shfl_xor_sync(0xffffffffu, mhi, 1));
        mhi = fmaxf(mhi, __shfl_xor_sync(0xffffffffu, mhi, 2));
        if (q == 0){ wred[wn*64 + rlo] = mlo; wred[wn*64 + rhi] = mhi; }
        __syncthreads();
        if (tid < 64){
            float nm = fmaxf(runm[tid], fmaxf(wred[tid], wred[64+tid]));
            fsc[tid] = __expf(runm[tid] - nm);
            runm[tid] = nm;
        }
        __syncthreads();

        // p = exp(L - m_new), rowsum, rescale Ua
        float Mlo = runm[rlo], Mhi = runm[rhi];
        float slo = 0.f, shi = 0.f;
        #pragma unroll
        for (int nt = 0; nt < 4; nt++){
            int c0 = wn*32 + nt*8 + 2*q;
            float p0 = __expf(L[nt][0]-Mlo), p1 = __expf(L[nt][1]-Mlo);
            float p2 = __expf(L[nt][2]-Mhi), p3 = __expf(L[nt][3]-Mhi);
            slo += p0 + p1; shi += p2 + p3;
            p_s[rlo*68 + c0] = f2tf(p0); p_s[rlo*68 + c0 + 1] = f2tf(p1);
            p_s[rhi*68 + c0] = f2tf(p2); p_s[rhi*68 + c0 + 1] = f2tf(p3);
        }
        slo += __shfl_xor_sync(0xffffffffu, slo, 1);
        slo += __shfl_xor_sync(0xffffffffu, slo, 2);
        shi += __shfl_xor_sync(0xffffffffu, shi, 1);
        shi += __shfl_xor_sync(0xffffffffu, shi, 2);
        if (q == 0){ wred[wn*64 + rlo] = slo; wred[wn*64 + rhi] = shi; }
        float fl = fsc[rlo], fh = fsc[rhi];
        #pragma unroll
        for (int nt2 = 0; nt2 < 8; nt2++){
            Ua[nt2][0] *= fl; Ua[nt2][1] *= fl;
            Ua[nt2][2] *= fh; Ua[nt2][3] *= fh;
        }
        __syncthreads();
        if (tid < 64) runs[tid] = runs[tid]*fsc[tid] + wred[tid] + wred[64+tid];

        // MMA2: Ua[64x128] += p @ E   (warp tile 16x64)
        #pragma unroll
        for (int ks = 0; ks < 8; ks++){
            int kb = ks*8;
            uint32_t a[4] = { p_s[rlo*68 + kb + q], p_s[rhi*68 + kb + q],
                              p_s[rlo*68 + kb + q + 4], p_s[rhi*68 + kb + q + 4] };
            #pragma unroll
            for (int nt2 = 0; nt2 < 8; nt2++){
                int na = wn*64 + nt2*8 + g;
                uint32_t b[2] = { E_s[(kb+q)*132 + na], E_s[(kb+q+4)*132 + na] };
                mma8(Ua[nt2], a, b);
            }
        }
    }

    // write partials
    size_t base = ((size_t)sp*NROWS + by*64);
    #pragma unroll
    for (int nt2 = 0; nt2 < 8; nt2++){
        int col = wn*64 + nt2*8 + 2*q;
        *(float2*)&g_Um[(base + rlo)*Dq + col] = make_float2(Ua[nt2][0], Ua[nt2][1]);
        *(float2*)&g_Um[(base + rhi)*Dq + col] = make_float2(Ua[nt2][2], Ua[nt2][3]);
    }
    if (tid < 64){
        g_mrow[sp*NROWS + by*64 + tid] = runm[tid];
        g_srow[sp*NROWS + by*64 + tid] = runs[tid];
    }
}

// combine split partials: U = sum_sp e^{m-M} Up / sum_sp e^{m-M} s
__global__ void k_flash_combine(){
    int row = blockIdx.x, d = threadIdx.x;
    __shared__ float ms[NSPLIT], ss[NSPLIT];
    if (d < NSPLIT){ ms[d] = g_mrow[d*NROWS + row]; ss[d] = g_srow[d*NROWS + row]; }
    __syncthreads();
    float M = -3.4e38f;
    for (int sp = 0; sp < NSPLIT; sp++) M = fmaxf(M, ms[sp]);
    float S = 0.f, U = 0.f;
    for (int sp = 0; sp < NSPLIT; sp++){
        float w = __expf(ms[sp] - M);
        S += w * ss[sp];
        U += w * g_Um[((size_t)sp*NROWS + row)*Dq + d];
    }
    g_U[row*Dq + d] = U / S;
}

// final logits: out[512,32000] = qz @ E^T   (tile 64x64, warp 16x32)
#define LOGIT_SMEM ((QZW + EW)*4)
__global__ void __launch_bounds__(256) k_logits(const float* __restrict__ E, float* __restrict__ out){
    extern __shared__ uint32_t sh[];
    uint32_t* qz_s = sh;
    uint32_t* E_s  = sh + QZW;
    int tid = threadIdx.x;
    int bx = blockIdx.x, by = blockIdx.y;
    int warp = tid>>5, lane = tid&31;
    int wm = warp&3, wn = warp>>2;
    int g = lane>>2, q = lane&3;
    {
        const float* A = &g_qz[(by*64)*Dq];
        const float* Eb = &E[(size_t)(bx*64)*Dq];
        #pragma unroll
        for (int it = 0; it < 8; it++){
            int i4 = tid + it*256;
            int r = i4 >> 5, c4 = (i4 & 31)*4;
            float4 v = *(const float4*)&A[r*Dq + c4];
            qz_s[r*132+c4+0]=f2tf(v.x); qz_s[r*132+c4+1]=f2tf(v.y);
            qz_s[r*132+c4+2]=f2tf(v.z); qz_s[r*132+c4+3]=f2tf(v.w);
            float4 e = *(const float4*)&Eb[r*Dq + c4];
            E_s[r*132+c4+0]=f2tf(e.x); E_s[r*132+c4+1]=f2tf(e.y);
            E_s[r*132+c4+2]=f2tf(e.z); E_s[r*132+c4+3]=f2tf(e.w);
        }
    }
    __syncthreads();
    int rlo = wm*16 + g, rhi = rlo + 8;
    float L[4][4];
    #pragma unroll
    for (int i = 0; i < 4; i++){ L[i][0]=0;L[i][1]=0;L[i][2]=0;L[i][3]=0; }
    const uint32_t* qrow = &qz_s[rlo*132 + q];
    #pragma unroll
    for (int ks = 0; ks < 16; ks++){
        int kb = ks*8;
        uint32_t a[4];
        a[0] = qrow[kb]; a[1] = qrow[kb + 8*132];
        a[2] = qrow[kb+4]; a[3] = qrow[kb+4 + 8*132];
        #pragma unroll
        for (int nt = 0; nt < 4; nt++){
            int nc = wn*32 + nt*8 + g;
            uint32_t b[2] = { E_s[nc*132 + kb + q], E_s[nc*132 + kb + q + 4] };
            mma8(L[nt], a, b);
        }
    }
    #pragma unroll
    for (int nt = 0; nt < 4; nt++){
        int col = bx*64 + wn*32 + nt*8 + 2*q;
        *(float2*)&out[(size_t)(by*64 + rlo)*Vq + col] = make_float2(L[nt][0], L[nt][1]);
        *(float2*)&out[(size_t)(by*64 + rhi)*Vq + col] = make_float2(L[nt][2], L[nt][3]);
    }
}

// ---------------- generic strided batched tf32 GEMM ----------------
// C[i,j] (+)= sum_k A[i,k]*B[k,j]; 64x64 tile, 8 warps (warp 16x32), k-stage 16.
__global__ void __launch_bounds__(256) k_gemm_tf(
    const float* __restrict__ A, const float* __restrict__ Bm, float* __restrict__ C,
    int K,
    int sAi, int sAk, int sBk, int sBj, int sCi, int sCj,
    int b3, int b2,
    int aB1, int aB2, int aB3,
    int bB1, int bB2, int bB3,
    int cB1, int cB2, int cB3,
    int accumulate)
{
    int bz = blockIdx.z;
    int i3 = bz % b3; int t_ = bz / b3; int i2 = t_ % b2; int i1 = t_ / b2;
    A  += (size_t)i1*aB1 + (size_t)i2*aB2 + (size_t)i3*aB3;
    Bm += (size_t)i1*bB1 + (size_t)i2*bB2 + (size_t)i3*bB3;
    C  += (size_t)i1*cB1 + (size_t)i2*cB2 + (size_t)i3*cB3;
    int m0 = blockIdx.y*64, n0 = blockIdx.x*64;

    __shared__ uint32_t As[64*20];   // [m][k], stride 20
    __shared__ uint32_t Bs[16*68];   // [k][n], stride 68

    int tid = threadIdx.x;
    int warp = tid>>5, lane = tid&31;
    int wm = warp&3, wn = warp>>2;
    int g = lane>>2, q = lane&3;
    float acc[4][4];
    #pragma unroll
    for (int i = 0; i < 4; i++){ acc[i][0]=0;acc[i][1]=0;acc[i][2]=0;acc[i][3]=0; }

    for (int k0 = 0; k0 < K; k0 += 16){
        #pragma unroll
        for (int p_ = 0; p_ < 4; p_++){
            int idx = tid + p_*256;
            int mn = idx & 63, kk = idx >> 6;
            As[mn*20 + kk] = f2tf(A [(size_t)(m0+mn)*sAi + (size_t)(k0+kk)*sAk]);
            Bs[kk*68 + mn] = f2tf(Bm[(size_t)(k0+kk)*sBk + (size_t)(n0+mn)*sBj]);
        }
        __syncthreads();
        #pragma unroll
        for (int kh = 0; kh < 2; kh++){
            int kk2 = kh*8;
            const uint32_t* ap = &As[(wm*16+g)*20 + kk2 + q];
            uint32_t a[4] = { ap[0], ap[8*20], ap[4], ap[8*20+4] };
            #pragma unroll
            for (int nt = 0; nt < 4; nt++){
                int n = wn*32 + nt*8 + g;
                uint32_t b[2] = { Bs[(kk2+q)*68 + n], Bs[(kk2+q+4)*68 + n] };
                mma8(acc[nt], a, b);
            }
        }
        __syncthreads();
    }
    int rlo = m0 + wm*16 + g, rhi = rlo + 8;
    #pragma unroll
    for (int nt = 0; nt < 4; nt++){
        int c0 = n0 + wn*32 + nt*8 + 2*q;
        float* p00 = &C[(size_t)rlo*sCi + (size_t)(c0  )*sCj];
        float* p01 = &C[(size_t)rlo*sCi + (size_t)(c0+1)*sCj];
        float* p10 = &C[(size_t)rhi*sCi + (size_t)(c0  )*sCj];
        float* p11 = &C[(size_t)rhi*sCi + (size_t)(c0+1)*sCj];
        if (accumulate){ *p00 += acc[nt][0]; *p01 += acc[nt][1]; *p10 += acc[nt][2]; *p11 += acc[nt][3]; }
        else           { *p00  = acc[nt][0]; *p01  = acc[nt][1]; *p10  = acc[nt][2]; *p11  = acc[nt][3]; }
    }
}

// ---------------- host ----------------
extern "C" void kernel_launch(void* const* d_in, const int* in_sizes, int n_in,
                              void* d_out, int out_size){
    const float* x      = (const float*)d_in[0];
    const int*   mask   = (const int*)  d_in[1];
    const float* E      = (const float*)d_in[2];
    const int*   m_mask = (const int*)  d_in[3];
    const float* T      = (const float*)d_in[4];
    float* out = (float*)d_out;

    cudaFuncSetAttribute(k_flash,  cudaFuncAttributeMaxDynamicSharedMemorySize, FLASH_SMEM);
    cudaFuncSetAttribute(k_logits, cudaFuncAttributeMaxDynamicSharedMemorySize, LOGIT_SMEM);

    void* qp;
    float *Pqz,*Pt1,*PF,*PHm,*Ps1,*Ps2,*PG,*PTp;
    cudaGetSymbolAddress(&qp, g_qz);  Pqz  = (float*)qp;
    cudaGetSymbolAddress(&qp, g_t1);  Pt1  = (float*)qp;
    cudaGetSymbolAddress(&qp, g_F);   PF   = (float*)qp;
    cudaGetSymbolAddress(&qp, g_Hm);  PHm  = (float*)qp;
    cudaGetSymbolAddress(&qp, g_s1);  Ps1  = (float*)qp;
    cudaGetSymbolAddress(&qp, g_s2);  Ps2  = (float*)qp;
    cudaGetSymbolAddress(&qp, g_G);   PG   = (float*)qp;
    cudaGetSymbolAddress(&qp, g_Tp);  PTp  = (float*)qp;

    // preprocessing
    k_meanE_part<<<128,128>>>(E);
    k_meanE_red<<<1,128>>>();
    k_permT<<<(2*Dq*Dq*Hq + 255)/256, 256>>>(T);
    k_compose_init<<<NROWS*Dq/256, 256>>>(x, m_mask);
    k_softmax128<<<NROWS, 128>>>(mask);

    for (int t = 0; t < 4; t++){
        // t1[z,k,i,(b,c)] = sum_a qz[z,i,a] T[k,a,(b,c)]   M=128 N=1024 K=128
        k_gemm_tf<<<dim3(16,2,8), 256>>>(Pqz, T, Pt1, 128,
            Dq,1,  DHq,1,  DHq,1,
            1,2,
            Lq*Dq,0,0,   0,Dq*DHq,0,   2*Lq*DHq,Lq*DHq,0,  0);

        // F[z,k,c,i,j] = sum_b t1[z,k,i,(b,c)] qz[z,j,b]   M=N=K=128
        k_gemm_tf<<<dim3(2,2,64), 256>>>(Pt1, Pqz, PF, 128,
            DHq,Hq,  1,Dq,  Lq,1,
            8,2,
            2*Lq*DHq,Lq*DHq,1,  Lq*Dq,0,0,  2*Hq*Lq*Lq,Hq*Lq*Lq,Lq*Lq,  0);

        k_hsoftmax<<<Bq*Hq*Lq, 128>>>(mask);

        // s1[z,k,i,(b,c)] = sum_j Hm[k,z,c,i,j] qz[z,j,b]
        k_gemm_tf<<<dim3(2,2,64), 256>>>(PHm, Pqz, Ps1, 128,
            Lq,1,  Dq,1,  DHq,Hq,
            8,2,
            Hq*Lq*Lq, Bq*Hq*Lq*Lq, Lq*Lq,   Lq*Dq,0,0,   2*Lq*DHq,Lq*DHq,1,  0);

        // s2[z,k,j,(a,c)] = sum_i Hm[k,z,c,i,j] qz[z,i,a]
        k_gemm_tf<<<dim3(2,2,64), 256>>>(PHm, Pqz, Ps2, 128,
            1,Lq,  Dq,1,  DHq,Hq,
            8,2,
            Hq*Lq*Lq, Bq*Hq*Lq*Lq, Lq*Lq,   Lq*Dq,0,0,   2*Lq*DHq,Lq*DHq,1,  0);

        // G[z,i,a]  = sum_{k,(b,c)} s1[z,k,i,m] T[k,a,m]       K=1024
        for (int k = 0; k < 2; k++)
            k_gemm_tf<<<dim3(2,2,4), 256>>>(Ps1 + (size_t)k*Lq*DHq, T + (size_t)k*Dq*DHq, PG, DHq,
                DHq,1,  1,DHq,  Dq,1,
                1,1,
                2*Lq*DHq,0,0,   0,0,0,   Lq*Dq,0,0,   (k==0)?0:1);

        // G[z,j,b] += sum_{k,(a,c)} s2[z,k,j,m] Tp[k,m,b]      K=1024
        for (int k = 0; k < 2; k++)
            k_gemm_tf<<<dim3(2,2,4), 256>>>(Ps2 + (size_t)k*Lq*DHq, PTp + (size_t)k*DHq*Dq, PG, DHq,
                DHq,1,  Dq,1,  Dq,1,
                1,1,
                2*Lq*DHq,0,0,   0,0,0,   Lq*Dq,0,0,   1);

        if (t == 0){
            k_compose_ueff<<<NROWS*Dq/256, 256>>>(x, m_mask, 0);
        } else {
            // fused: U = softmax(qz_prev @ E^T) @ E, split over V
            k_flash<<<dim3(NSPLIT, 8), 256, FLASH_SMEM>>>(E);
            k_flash_combine<<<NROWS, 128>>>();
            k_compose_ueff<<<NROWS*Dq/256, 256>>>(x, m_mask, 1);
        }
        k_softmax128<<<NROWS, 128>>>(mask);

        if (t == 3){
            k_logits<<<dim3(Vq/64, 8), 256, LOGIT_SMEM>>>(E, out);
        }
    }
}

// round 4
// speedup vs baseline: 4.3622x; 3.1618x over previous
#include <cuda_runtime.h>
#include <cstdint>
#include <cstddef>

// Problem constants
#define Bq 4
#define Lq 128
#define Dq 128
#define Hq 8
#define Vq 32000
#define DHq (Dq*Hq)          // 1024
#define NEGC 1e9f
#define NROWS (Bq*Lq)        // 512
#define NSPLIT 50
#define VCHUNK (Vq/NSPLIT)   // 640
#define GPARTS 32            // 2 terms x 2 k x 8 K-splits

// ---------------- scratch (device globals) ----------------
__device__ float g_meanE_part[128*128];
__device__ float g_meanE[Dq];
__device__ float g_Tp[2*DHq*Dq];                 // Tp[k][(a*H+c)][b]
__device__ float g_qz[NROWS*Dq];
__device__ float g_zlog[NROWS*Dq];
__device__ float g_t1[Bq*2*Lq*DHq];              // [z][k][i][(b*H+c)]
__device__ float g_F[Bq*2*Hq*Lq*Lq];             // [z][k][c][i][j]
__device__ float g_Hm[2*Bq*Hq*Lq*Lq];            // [k][z][c][i][j]
__device__ float g_s1[Bq*2*Lq*DHq];
__device__ float g_s2[Bq*2*Lq*DHq];
__device__ float g_Gpart[(size_t)GPARTS*NROWS*Dq];
__device__ float g_Um[(size_t)NSPLIT*NROWS*Dq];  // flash partial accumulators
__device__ float g_mrow[NSPLIT*NROWS];
__device__ float g_srow[NSPLIT*NROWS];

// ---------------- tf32 mma helpers ----------------
__device__ __forceinline__ uint32_t f2tf(float f){
    uint32_t u; asm("cvt.rna.tf32.f32 %0, %1;" : "=r"(u) : "f"(f)); return u;
}
__device__ __forceinline__ void mma8(float c[4], const uint32_t a[4], const uint32_t b[2]){
    asm("mma.sync.aligned.m16n8k8.row.col.f32.tf32.tf32.f32 "
        "{%0,%1,%2,%3},{%4,%5,%6,%7},{%8,%9},{%0,%1,%2,%3};"
        : "+f"(c[0]),"+f"(c[1]),"+f"(c[2]),"+f"(c[3])
        : "r"(a[0]),"r"(a[1]),"r"(a[2]),"r"(a[3]),"r"(b[0]),"r"(b[1]));
}

// ---------------- small kernels ----------------
__global__ void k_meanE_part(const float* __restrict__ E){
    int b = blockIdx.x, t = threadIdx.x;
    float s = 0.f;
    int v0 = b * (Vq/128);
    for (int v = 0; v < Vq/128; v++) s += E[(size_t)(v0+v)*Dq + t];
    g_meanE_part[b*128 + t] = s;
}
__global__ void k_meanE_red(){
    int t = threadIdx.x;
    float s = 0.f;
    for (int b = 0; b < 128; b++) s += g_meanE_part[b*128 + t];
    g_meanE[t] = s / (float)Vq;
}

__global__ void k_permT(const float* __restrict__ T){
    int idx = blockIdx.x*256 + threadIdx.x;
    if (idx >= 2*Dq*Dq*Hq) return;
    int c = idx % Hq;
    int b = (idx/Hq) % Dq;
    int a = (idx/(Hq*Dq)) % Dq;
    int k = idx/(Hq*Dq*Dq);
    g_Tp[((size_t)k*DHq + a*Hq + c)*Dq + b] = T[idx];
}

__global__ void k_compose_init(const float* __restrict__ x, const int* __restrict__ m_mask){
    int idx = blockIdx.x*256 + threadIdx.x;
    int d = idx % Dq, row = idx / Dq;
    float mm = (float)m_mask[row];
    g_zlog[idx] = x[idx]*(1.f-mm) + g_meanE[d]*mm;
}

__global__ void k_softmax128(const int* __restrict__ mask){
    int row = blockIdx.x, t = threadIdx.x;
    float v = g_zlog[row*Dq + t];
    __shared__ float r1[4], r2[4];
    float m = v;
    #pragma unroll
    for (int o = 16; o; o >>= 1) m = fmaxf(m, __shfl_xor_sync(0xffffffffu, m, o));
    if ((t&31)==0) r1[t>>5] = m;
    __syncthreads();
    m = fmaxf(fmaxf(r1[0],r1[1]), fmaxf(r1[2],r1[3]));
    float e = __expf(v - m);
    float s = e;
    #pragma unroll
    for (int o = 16; o; o >>= 1) s += __shfl_xor_sync(0xffffffffu, s, o);
    if ((t&31)==0) r2[t>>5] = s;
    __syncthreads();
    s = r2[0]+r2[1]+r2[2]+r2[3];
    float keep = (mask[row] != 0) ? 1.f : 0.f;
    g_qz[row*Dq + t] = e/s*keep;
}

__global__ void k_hsoftmax(const int* __restrict__ mask){
    int bi = blockIdx.x;                    // z*H*L + c*L + i
    int i = bi & (Lq-1);
    int c = (bi >> 7) & (Hq-1);
    int z = bi >> 10;
    int j = threadIdx.x;
    bool mok = (mask[z*Lq+i] != 0) && (mask[z*Lq+j] != 0);
    float v;
    if (!mok || j == i) v = -NEGC;
    else if (j > i) v = g_F[((((size_t)z*2+0)*Hq+c)*Lq+i)*Lq + j];
    else            v = g_F[((((size_t)z*2+1)*Hq+c)*Lq+i)*Lq + j];
    __shared__ float r1[4], r2[4];
    float m = v;
    #pragma unroll
    for (int o = 16; o; o >>= 1) m = fmaxf(m, __shfl_xor_sync(0xffffffffu, m, o));
    if ((j&31)==0) r1[j>>5] = m;
    __syncthreads();
    m = fmaxf(fmaxf(r1[0],r1[1]), fmaxf(r1[2],r1[3]));
    float e = __expf(v - m);
    float s = e;
    #pragma unroll
    for (int o = 16; o; o >>= 1) s += __shfl_xor_sync(0xffffffffu, s, o);
    if ((j&31)==0) r2[j>>5] = s;
    __syncthreads();
    s = r2[0]+r2[1]+r2[2]+r2[3];
    float p = e/s;
    size_t o0 = ((((size_t)0*Bq+z)*Hq+c)*Lq+i)*Lq + j;
    size_t o1 = ((((size_t)1*Bq+z)*Hq+c)*Lq+i)*Lq + j;
    g_Hm[o0] = (j > i) ? p : 0.f;
    g_Hm[o1] = (j < i) ? p : 0.f;
}

// fused per-row: G partial reduce + flash combine + compose unary + Z-softmax
__global__ void k_fuse_row(const int* __restrict__ mask, const float* __restrict__ x,
                           const int* __restrict__ m_mask, int mode){
    int row = blockIdx.x, d = threadIdx.x;
    __shared__ float ms[NSPLIT], ss[NSPLIT];
    __shared__ float r1[4], r2[4];

    float Gv = 0.f;
    #pragma unroll 8
    for (int p = 0; p < GPARTS; p++) Gv += g_Gpart[((size_t)p*NROWS + row)*Dq + d];

    float u;
    if (mode){
        if (d < NSPLIT){ ms[d] = g_mrow[d*NROWS + row]; ss[d] = g_srow[d*NROWS + row]; }
        __syncthreads();
        float M = -3.4e38f;
        #pragma unroll 10
        for (int sp = 0; sp < NSPLIT; sp++) M = fmaxf(M, ms[sp]);
        float S = 0.f, Uv = 0.f;
        for (int sp = 0; sp < NSPLIT; sp++){
            float w = __expf(ms[sp] - M);
            S  += w * ss[sp];
            Uv += w * g_Um[((size_t)sp*NROWS + row)*Dq + d];
        }
        u = Uv / S;
    } else {
        u = g_meanE[d];
    }
    float mm = (float)m_mask[row];
    float v = x[row*Dq + d]*(1.f - mm) + u*mm + Gv;

    float m = v;
    #pragma unroll
    for (int o = 16; o; o >>= 1) m = fmaxf(m, __shfl_xor_sync(0xffffffffu, m, o));
    if ((d&31)==0) r1[d>>5] = m;
    __syncthreads();
    m = fmaxf(fmaxf(r1[0],r1[1]), fmaxf(r1[2],r1[3]));
    float e = __expf(v - m);
    float s = e;
    #pragma unroll
    for (int o = 16; o; o >>= 1) s += __shfl_xor_sync(0xffffffffu, s, o);
    if ((d&31)==0) r2[d>>5] = s;
    __syncthreads();
    s = r2[0]+r2[1]+r2[2]+r2[3];
    float keep = (mask[row] != 0) ? 1.f : 0.f;
    g_qz[row*Dq + d] = e/s*keep;
}

// ---------------- fused flash V kernel ----------------
#define QZW (64*132)
#define EW  (64*132)
#define PW  (64*68)
#define FLASH_SMEM ((QZW + EW + PW + 64*3 + 128)*4)

__global__ void __launch_bounds__(256) k_flash(const float* __restrict__ E){
    extern __shared__ uint32_t sh[];
    uint32_t* qz_s = sh;
    uint32_t* E_s  = sh + QZW;
    uint32_t* p_s  = E_s + EW;
    float* runm = (float*)(p_s + PW);
    float* runs = runm + 64;
    float* fsc  = runs + 64;
    float* wred = fsc + 64;            // [2][64]

    int tid = threadIdx.x;
    int sp = blockIdx.x, by = blockIdx.y;
    int warp = tid>>5, lane = tid&31;
    int wm = warp&3, wn = warp>>2;
    int g = lane>>2, q = lane&3;

    {
        const float* A = &g_qz[(by*64)*Dq];
        #pragma unroll
        for (int it = 0; it < 8; it++){
            int i4 = tid + it*256;
            int r = i4 >> 5, c4 = (i4 & 31)*4;
            float4 v = *(const float4*)&A[r*Dq + c4];
            qz_s[r*132+c4+0]=f2tf(v.x); qz_s[r*132+c4+1]=f2tf(v.y);
            qz_s[r*132+c4+2]=f2tf(v.z); qz_s[r*132+c4+3]=f2tf(v.w);
        }
    }
    if (tid < 64){ runm[tid] = -3.4e38f; runs[tid] = 0.f; }

    float Ua[8][4];
    #pragma unroll
    for (int i = 0; i < 8; i++){ Ua[i][0]=0;Ua[i][1]=0;Ua[i][2]=0;Ua[i][3]=0; }

    int v0 = sp*VCHUNK;
    int rlo = wm*16 + g, rhi = rlo + 8;

    for (int ci = 0; ci < VCHUNK/64; ci++){
        __syncthreads();
        const float* Eb = &E[(size_t)(v0 + ci*64)*Dq];
        #pragma unroll
        for (int it = 0; it < 8; it++){
            int i4 = tid + it*256;
            int r = i4 >> 5, c4 = (i4 & 31)*4;
            float4 v = *(const float4*)&Eb[r*Dq + c4];
            E_s[r*132+c4+0]=f2tf(v.x); E_s[r*132+c4+1]=f2tf(v.y);
            E_s[r*132+c4+2]=f2tf(v.z); E_s[r*132+c4+3]=f2tf(v.w);
        }
        __syncthreads();

        float L[4][4];
        #pragma unroll
        for (int i = 0; i < 4; i++){ L[i][0]=0;L[i][1]=0;L[i][2]=0;L[i][3]=0; }
        const uint32_t* qrow = &qz_s[rlo*132 + q];
        #pragma unroll
        for (int ks = 0; ks < 16; ks++){
            int kb = ks*8;
            uint32_t a[4];
            a[0] = qrow[kb]; a[1] = qrow[kb + 8*132];
            a[2] = qrow[kb+4]; a[3] = qrow[kb+4 + 8*132];
            #pragma unroll
            for (int nt = 0; nt < 4; nt++){
                int nc = wn*32 + nt*8 + g;
                uint32_t b[2] = { E_s[nc*132 + kb + q], E_s[nc*132 + kb + q + 4] };
                mma8(L[nt], a, b);
            }
        }

        float mlo = -3.4e38f, mhi = -3.4e38f;
        #pragma unroll
        for (int nt = 0; nt < 4; nt++){
            mlo = fmaxf(mlo, fmaxf(L[nt][0], L[nt][1]));
            mhi = fmaxf(mhi, fmaxf(L[nt][2], L[nt][3]));
        }
        mlo = fmaxf(mlo, __shfl_xor_sync(0xffffffffu, mlo, 1));
        mlo = fmaxf(mlo, __shfl_xor_sync(0xffffffffu, mlo, 2));
        mhi = fmaxf(mhi, __shfl_xor_sync(0xffffffffu, mhi, 1));
        mhi = fmaxf(mhi, __shfl_xor_sync(0xffffffffu, mhi, 2));
        if (q == 0){ wred[wn*64 + rlo] = mlo; wred[wn*64 + rhi] = mhi; }
        __syncthreads();
        if (tid < 64){
            float nm = fmaxf(runm[tid], fmaxf(wred[tid], wred[64+tid]));
            fsc[tid] = __expf(runm[tid] - nm);
            runm[tid] = nm;
        }
        __syncthreads();

        float Mlo = runm[rlo], Mhi = runm[rhi];
        float slo = 0.f, shi = 0.f;
        #pragma unroll
        for (int nt = 0; nt < 4; nt++){
            int c0 = wn*32 + nt*8 + 2*q;
            float p0 = __expf(L[nt][0]-Mlo), p1 = __expf(L[nt][1]-Mlo);
            float p2 = __expf(L[nt][2]-Mhi), p3 = __expf(L[nt][3]-Mhi);
            slo += p0 + p1; shi += p2 + p3;
            p_s[rlo*68 + c0] = f2tf(p0); p_s[rlo*68 + c0 + 1] = f2tf(p1);
            p_s[rhi*68 + c0] = f2tf(p2); p_s[rhi*68 + c0 + 1] = f2tf(p3);
        }
        slo += __shfl_xor_sync(0xffffffffu, slo, 1);
        slo += __shfl_xor_sync(0xffffffffu, slo, 2);
        shi += __shfl_xor_sync(0xffffffffu, shi, 1);
        shi += __shfl_xor_sync(0xffffffffu, shi, 2);
        if (q == 0){ wred[wn*64 + rlo] = slo; wred[wn*64 + rhi] = shi; }
        float fl = fsc[rlo], fh = fsc[rhi];
        #pragma unroll
        for (int nt2 = 0; nt2 < 8; nt2++){
            Ua[nt2][0] *= fl; Ua[nt2][1] *= fl;
            Ua[nt2][2] *= fh; Ua[nt2][3] *= fh;
        }
        __syncthreads();
        if (tid < 64) runs[tid] = runs[tid]*fsc[tid] + wred[tid] + wred[64+tid];

        #pragma unroll
        for (int ks = 0; ks < 8; ks++){
            int kb = ks*8;
            uint32_t a[4] = { p_s[rlo*68 + kb + q], p_s[rhi*68 + kb + q],
                              p_s[rlo*68 + kb + q + 4], p_s[rhi*68 + kb + q + 4] };
            #pragma unroll
            for (int nt2 = 0; nt2 < 8; nt2++){
                int na = wn*64 + nt2*8 + g;
                uint32_t b[2] = { E_s[(kb+q)*132 + na], E_s[(kb+q+4)*132 + na] };
                mma8(Ua[nt2], a, b);
            }
        }
    }

    size_t base = ((size_t)sp*NROWS + by*64);
    #pragma unroll
    for (int nt2 = 0; nt2 < 8; nt2++){
        int col = wn*64 + nt2*8 + 2*q;
        *(float2*)&g_Um[(base + rlo)*Dq + col] = make_float2(Ua[nt2][0], Ua[nt2][1]);
        *(float2*)&g_Um[(base + rhi)*Dq + col] = make_float2(Ua[nt2][2], Ua[nt2][3]);
    }
    if (tid < 64){
        g_mrow[sp*NROWS + by*64 + tid] = runm[tid];
        g_srow[sp*NROWS + by*64 + tid] = runs[tid];
    }
}

// final logits: out[512,32000] = qz @ E^T
#define LOGIT_SMEM ((QZW + EW)*4)
__global__ void __launch_bounds__(256) k_logits(const float* __restrict__ E, float* __restrict__ out){
    extern __shared__ uint32_t sh[];
    uint32_t* qz_s = sh;
    uint32_t* E_s  = sh + QZW;
    int tid = threadIdx.x;
    int bx = blockIdx.x, by = blockIdx.y;
    int warp = tid>>5, lane = tid&31;
    int wm = warp&3, wn = warp>>2;
    int g = lane>>2, q = lane&3;
    {
        const float* A = &g_qz[(by*64)*Dq];
        const float* Eb = &E[(size_t)(bx*64)*Dq];
        #pragma unroll
        for (int it = 0; it < 8; it++){
            int i4 = tid + it*256;
            int r = i4 >> 5, c4 = (i4 & 31)*4;
            float4 v = *(const float4*)&A[r*Dq + c4];
            qz_s[r*132+c4+0]=f2tf(v.x); qz_s[r*132+c4+1]=f2tf(v.y);
            qz_s[r*132+c4+2]=f2tf(v.z); qz_s[r*132+c4+3]=f2tf(v.w);
            float4 e = *(const float4*)&Eb[r*Dq + c4];
            E_s[r*132+c4+0]=f2tf(e.x); E_s[r*132+c4+1]=f2tf(e.y);
            E_s[r*132+c4+2]=f2tf(e.z); E_s[r*132+c4+3]=f2tf(e.w);
        }
    }
    __syncthreads();
    int rlo = wm*16 + g, rhi = rlo + 8;
    float L[4][4];
    #pragma unroll
    for (int i = 0; i < 4; i++){ L[i][0]=0;L[i][1]=0;L[i][2]=0;L[i][3]=0; }
    const uint32_t* qrow = &qz_s[rlo*132 + q];
    #pragma unroll
    for (int ks = 0; ks < 16; ks++){
        int kb = ks*8;
        uint32_t a[4];
        a[0] = qrow[kb]; a[1] = qrow[kb + 8*132];
        a[2] = qrow[kb+4]; a[3] = qrow[kb+4 + 8*132];
        #pragma unroll
        for (int nt = 0; nt < 4; nt++){
            int nc = wn*32 + nt*8 + g;
            uint32_t b[2] = { E_s[nc*132 + kb + q], E_s[nc*132 + kb + q + 4] };
            mma8(L[nt], a, b);
        }
    }
    #pragma unroll
    for (int nt = 0; nt < 4; nt++){
        int col = bx*64 + wn*32 + nt*8 + 2*q;
        *(float2*)&out[(size_t)(by*64 + rlo)*Vq + col] = make_float2(L[nt][0], L[nt][1]);
        *(float2*)&out[(size_t)(by*64 + rhi)*Vq + col] = make_float2(L[nt][2], L[nt][3]);
    }
}

// ---------------- generic strided batched tf32 GEMM ----------------
// C[i,j] = sum_k A[i,k]*B[k,j]; 64x64 tile, 8 warps (warp 16x32), k-stage 16.
// aKfast/bKfast: stage smem sweeping k-fast (use when the k-stride is 1).
__global__ void __launch_bounds__(256) k_gemm_tf(
    const float* __restrict__ A, const float* __restrict__ Bm, float* __restrict__ C,
    int K,
    int sAi, int sAk, int sBk, int sBj, int sCi, int sCj,
    int b3, int b2,
    int aB1, int aB2, int aB3,
    int bB1, int bB2, int bB3,
    int cB1, int cB2, int cB3,
    int aKfast, int bKfast)
{
    int bz = blockIdx.z;
    int i3 = bz % b3; int t_ = bz / b3; int i2 = t_ % b2; int i1 = t_ / b2;
    A  += (size_t)i1*aB1 + (size_t)i2*aB2 + (size_t)i3*aB3;
    Bm += (size_t)i1*bB1 + (size_t)i2*bB2 + (size_t)i3*bB3;
    C  += (size_t)i1*cB1 + (size_t)i2*cB2 + (size_t)i3*cB3;
    int m0 = blockIdx.y*64, n0 = blockIdx.x*64;

    __shared__ uint32_t As[64*20];   // [m][k], stride 20
    __shared__ uint32_t Bs[16*68];   // [k][n], stride 68

    int tid = threadIdx.x;
    int warp = tid>>5, lane = tid&31;
    int wm = warp&3, wn = warp>>2;
    int g = lane>>2, q = lane&3;
    float acc[4][4];
    #pragma unroll
    for (int i = 0; i < 4; i++){ acc[i][0]=0;acc[i][1]=0;acc[i][2]=0;acc[i][3]=0; }

    for (int k0 = 0; k0 < K; k0 += 16){
        if (aKfast){
            #pragma unroll
            for (int p_ = 0; p_ < 4; p_++){
                int idx = tid + p_*256;
                int kk = idx & 15, mn = idx >> 4;
                As[mn*20 + kk] = f2tf(A[(size_t)(m0+mn)*sAi + (size_t)(k0+kk)*sAk]);
            }
        } else {
            #pragma unroll
            for (int p_ = 0; p_ < 4; p_++){
                int idx = tid + p_*256;
                int mn = idx & 63, kk = idx >> 6;
                As[mn*20 + kk] = f2tf(A[(size_t)(m0+mn)*sAi + (size_t)(k0+kk)*sAk]);
            }
        }
        if (bKfast){
            #pragma unroll
            for (int p_ = 0; p_ < 4; p_++){
                int idx = tid + p_*256;
                int kk = idx & 15, mn = idx >> 4;
                Bs[kk*68 + mn] = f2tf(Bm[(size_t)(k0+kk)*sBk + (size_t)(n0+mn)*sBj]);
            }
        } else {
            #pragma unroll
            for (int p_ = 0; p_ < 4; p_++){
                int idx = tid + p_*256;
                int mn = idx & 63, kk = idx >> 6;
                Bs[kk*68 + mn] = f2tf(Bm[(size_t)(k0+kk)*sBk + (size_t)(n0+mn)*sBj]);
            }
        }
        __syncthreads();
        #pragma unroll
        for (int kh = 0; kh < 2; kh++){
            int kk2 = kh*8;
            const uint32_t* ap = &As[(wm*16+g)*20 + kk2 + q];
            uint32_t a[4] = { ap[0], ap[8*20], ap[4], ap[8*20+4] };
            #pragma unroll
            for (int nt = 0; nt < 4; nt++){
                int n = wn*32 + nt*8 + g;
                uint32_t b[2] = { Bs[(kk2+q)*68 + n], Bs[(kk2+q+4)*68 + n] };
                mma8(acc[nt], a, b);
            }
        }
        __syncthreads();
    }
    int rlo = m0 + wm*16 + g, rhi = rlo + 8;
    #pragma unroll
    for (int nt = 0; nt < 4; nt++){
        int c0 = n0 + wn*32 + nt*8 + 2*q;
        C[(size_t)rlo*sCi + (size_t)(c0  )*sCj] = acc[nt][0];
        C[(size_t)rlo*sCi + (size_t)(c0+1)*sCj] = acc[nt][1];
        C[(size_t)rhi*sCi + (size_t)(c0  )*sCj] = acc[nt][2];
        C[(size_t)rhi*sCi + (size_t)(c0+1)*sCj] = acc[nt][3];
    }
}

// ---------------- host ----------------
extern "C" void kernel_launch(void* const* d_in, const int* in_sizes, int n_in,
                              void* d_out, int out_size){
    const float* x      = (const float*)d_in[0];
    const int*   mask   = (const int*)  d_in[1];
    const float* E      = (const float*)d_in[2];
    const int*   m_mask = (const int*)  d_in[3];
    const float* T      = (const float*)d_in[4];
    float* out = (float*)d_out;

    cudaFuncSetAttribute(k_flash,  cudaFuncAttributeMaxDynamicSharedMemorySize, FLASH_SMEM);
    cudaFuncSetAttribute(k_logits, cudaFuncAttributeMaxDynamicSharedMemorySize, LOGIT_SMEM);

    void* qp;
    float *Pqz,*Pt1,*PF,*PHm,*Ps1,*Ps2,*PTp,*PGp;
    cudaGetSymbolAddress(&qp, g_qz);    Pqz = (float*)qp;
    cudaGetSymbolAddress(&qp, g_t1);    Pt1 = (float*)qp;
    cudaGetSymbolAddress(&qp, g_F);     PF  = (float*)qp;
    cudaGetSymbolAddress(&qp, g_Hm);    PHm = (float*)qp;
    cudaGetSymbolAddress(&qp, g_s1);    Ps1 = (float*)qp;
    cudaGetSymbolAddress(&qp, g_s2);    Ps2 = (float*)qp;
    cudaGetSymbolAddress(&qp, g_Tp);    PTp = (float*)qp;
    cudaGetSymbolAddress(&qp, g_Gpart); PGp = (float*)qp;

    // preprocessing
    k_meanE_part<<<128,128>>>(E);
    k_meanE_red<<<1,128>>>();
    k_permT<<<(2*Dq*Dq*Hq + 255)/256, 256>>>(T);
    k_compose_init<<<NROWS*Dq/256, 256>>>(x, m_mask);
    k_softmax128<<<NROWS, 128>>>(mask);

    for (int t = 0; t < 4; t++){
        // t1[z,k,i,(b,c)] = sum_a qz[z,i,a] T[k,a,(b,c)]   M=128 N=1024 K=128
        k_gemm_tf<<<dim3(16,2,8), 256>>>(Pqz, T, Pt1, 128,
            Dq,1,  DHq,1,  DHq,1,
            1,2,
            Lq*Dq,0,0,   0,Dq*DHq,0,   2*Lq*DHq,Lq*DHq,0,
            1,0);   // A k-stride 1 -> k-fast; B j-stride 1 -> row-fast

        // F[z,k,c,i,j] = sum_b t1[z,k,i,(b,c)] qz[z,j,b]   M=N=K=128
        k_gemm_tf<<<dim3(2,2,64), 256>>>(Pt1, Pqz, PF, 128,
            DHq,Hq,  1,Dq,  Lq,1,
            8,2,
            2*Lq*DHq,Lq*DHq,1,  Lq*Dq,0,0,  2*Hq*Lq*Lq,Hq*Lq*Lq,Lq*Lq,
            1,1);   // A k-stride 8 (k-fast reduces to 8 sectors); B k-stride 1

        k_hsoftmax<<<Bq*Hq*Lq, 128>>>(mask);

        // s1[z,k,i,(b,c)] = sum_j Hm[k,z,c,i,j] qz[z,j,b]
        k_gemm_tf<<<dim3(2,2,64), 256>>>(PHm, Pqz, Ps1, 128,
            Lq,1,  Dq,1,  DHq,Hq,
            8,2,
            Hq*Lq*Lq, Bq*Hq*Lq*Lq, Lq*Lq,   Lq*Dq,0,0,   2*Lq*DHq,Lq*DHq,1,
            1,0);   // A k-stride 1; B j-stride 1

        // s2[z,k,j,(a,c)] = sum_i Hm[k,z,c,i,j] qz[z,i,a]
        k_gemm_tf<<<dim3(2,2,64), 256>>>(PHm, Pqz, Ps2, 128,
            1,Lq,  Dq,1,  DHq,Hq,
            8,2,
            Hq*Lq*Lq, Bq*Hq*Lq*Lq, Lq*Lq,   Lq*Dq,0,0,   2*Lq*DHq,Lq*DHq,1,
            0,0);   // A i-stride 1; B j-stride 1

        // G term 1 (split-K): parts[ (k*8+sk) ][z,i,a] = sum_{m chunk} s1[z,k,i,m] T[k,a,m]
        // batch dims: b3=8 (sk), b2=2 (k), i1=z (4)  -> grid.z = 64
        k_gemm_tf<<<dim3(2,2,64), 256>>>(Ps1, T, PGp, 128,
            DHq,1,  1,DHq,  Dq,1,
            8,2,
            2*Lq*DHq, Lq*DHq, 128,
            0,        Dq*DHq, 128,
            Lq*Dq,    8*NROWS*Dq, NROWS*Dq,
            1,1);   // A k-stride 1; B k-stride 1

        // G term 2 (split-K): parts[16 + k*8+sk][z,j,b] = sum_{m chunk} s2[z,k,j,m] Tp[k,m,b]
        k_gemm_tf<<<dim3(2,2,64), 256>>>(Ps2, PTp, PGp + (size_t)16*NROWS*Dq, 128,
            DHq,1,  Dq,1,  Dq,1,
            8,2,
            2*Lq*DHq, Lq*DHq, 128,
            0,        DHq*Dq, 128*Dq,
            Lq*Dq,    8*NROWS*Dq, NROWS*Dq,
            1,0);   // A k-stride 1; B j-stride 1

        if (t > 0){
            // fused: U = softmax(qz_prev @ E^T) @ E, split over V
            k_flash<<<dim3(NSPLIT, 8), 256, FLASH_SMEM>>>(E);
        }
        // fused: G-reduce + flash-combine + compose + Z softmax
        k_fuse_row<<<NROWS, 128>>>(mask, x, m_mask, (t > 0) ? 1 : 0);

        if (t == 3){
            k_logits<<<dim3(Vq/64, 8), 256, LOGIT_SMEM>>>(E, out);
        }
    }
}

// round 5
// speedup vs baseline: 4.7203x; 1.0821x over previous
#include <cuda_runtime.h>
#include <cstdint>
#include <cstddef>

// Problem constants
#define Bq 4
#define Lq 128
#define Dq 128
#define Hq 8
#define Vq 32000
#define DHq (Dq*Hq)          // 1024
#define NEGC 1e9f
#define NROWS (Bq*Lq)        // 512
#define NSPLIT 50
#define VCHUNK (Vq/NSPLIT)   // 640
#define GPARTS 32            // 2 terms x 2 k x 8 K-splits

// ---------------- scratch (device globals) ----------------
__device__ float g_meanE_part[128*128];
__device__ float g_meanE[Dq];
__device__ float g_Tp[2*DHq*Dq];                 // Tp[k][(a*H+c)][b]
__device__ float g_qz[NROWS*Dq];
__device__ float g_zlog[NROWS*Dq];
__device__ float g_t1[Bq*2*Lq*DHq];              // [z][k][i][(b*H+c)]
__device__ float g_F[Bq*2*Hq*Lq*Lq];             // [z][k][c][i][j]
__device__ float g_Hm[2*Bq*Hq*Lq*Lq];            // [k][z][c][i][j]
__device__ float g_s1[Bq*2*Lq*DHq];
__device__ float g_s2[Bq*2*Lq*DHq];
__device__ float g_Gpart[(size_t)GPARTS*NROWS*Dq];
__device__ float g_Um[(size_t)NSPLIT*NROWS*Dq];  // flash partial accumulators
__device__ float g_srow[NSPLIT*NROWS];

// ---------------- tf32 mma helpers ----------------
__device__ __forceinline__ uint32_t f2tf(float f){
    uint32_t u; asm("cvt.rna.tf32.f32 %0, %1;" : "=r"(u) : "f"(f)); return u;
}
__device__ __forceinline__ void mma8(float c[4], const uint32_t a[4], const uint32_t b[2]){
    asm("mma.sync.aligned.m16n8k8.row.col.f32.tf32.tf32.f32 "
        "{%0,%1,%2,%3},{%4,%5,%6,%7},{%8,%9},{%0,%1,%2,%3};"
        : "+f"(c[0]),"+f"(c[1]),"+f"(c[2]),"+f"(c[3])
        : "r"(a[0]),"r"(a[1]),"r"(a[2]),"r"(a[3]),"r"(b[0]),"r"(b[1]));
}

// ---------------- small kernels ----------------
__global__ void k_meanE_part(const float* __restrict__ E){
    int b = blockIdx.x, t = threadIdx.x;
    float s = 0.f;
    int v0 = b * (Vq/128);
    for (int v = 0; v < Vq/128; v++) s += E[(size_t)(v0+v)*Dq + t];
    g_meanE_part[b*128 + t] = s;
}
__global__ void k_meanE_red(){
    int t = threadIdx.x;
    float s = 0.f;
    for (int b = 0; b < 128; b++) s += g_meanE_part[b*128 + t];
    g_meanE[t] = s / (float)Vq;
}

__global__ void k_permT(const float* __restrict__ T){
    int idx = blockIdx.x*256 + threadIdx.x;
    if (idx >= 2*Dq*Dq*Hq) return;
    int c = idx % Hq;
    int b = (idx/Hq) % Dq;
    int a = (idx/(Hq*Dq)) % Dq;
    int k = idx/(Hq*Dq*Dq);
    g_Tp[((size_t)k*DHq + a*Hq + c)*Dq + b] = T[idx];
}

__global__ void k_compose_init(const float* __restrict__ x, const int* __restrict__ m_mask){
    int idx = blockIdx.x*256 + threadIdx.x;
    int d = idx % Dq, row = idx / Dq;
    float mm = (float)m_mask[row];
    g_zlog[idx] = x[idx]*(1.f-mm) + g_meanE[d]*mm;
}

__global__ void k_softmax128(const int* __restrict__ mask){
    int row = blockIdx.x, t = threadIdx.x;
    float v = g_zlog[row*Dq + t];
    __shared__ float r1[4], r2[4];
    float m = v;
    #pragma unroll
    for (int o = 16; o; o >>= 1) m = fmaxf(m, __shfl_xor_sync(0xffffffffu, m, o));
    if ((t&31)==0) r1[t>>5] = m;
    __syncthreads();
    m = fmaxf(fmaxf(r1[0],r1[1]), fmaxf(r1[2],r1[3]));
    float e = __expf(v - m);
    float s = e;
    #pragma unroll
    for (int o = 16; o; o >>= 1) s += __shfl_xor_sync(0xffffffffu, s, o);
    if ((t&31)==0) r2[t>>5] = s;
    __syncthreads();
    s = r2[0]+r2[1]+r2[2]+r2[3];
    float keep = (mask[row] != 0) ? 1.f : 0.f;
    g_qz[row*Dq + t] = e/s*keep;
}

__global__ void k_hsoftmax(const int* __restrict__ mask){
    int bi = blockIdx.x;                    // z*H*L + c*L + i
    int i = bi & (Lq-1);
    int c = (bi >> 7) & (Hq-1);
    int z = bi >> 10;
    int j = threadIdx.x;
    bool mok = (mask[z*Lq+i] != 0) && (mask[z*Lq+j] != 0);
    float v;
    if (!mok || j == i) v = -NEGC;
    else if (j > i) v = g_F[((((size_t)z*2+0)*Hq+c)*Lq+i)*Lq + j];
    else            v = g_F[((((size_t)z*2+1)*Hq+c)*Lq+i)*Lq + j];
    __shared__ float r1[4], r2[4];
    float m = v;
    #pragma unroll
    for (int o = 16; o; o >>= 1) m = fmaxf(m, __shfl_xor_sync(0xffffffffu, m, o));
    if ((j&31)==0) r1[j>>5] = m;
    __syncthreads();
    m = fmaxf(fmaxf(r1[0],r1[1]), fmaxf(r1[2],r1[3]));
    float e = __expf(v - m);
    float s = e;
    #pragma unroll
    for (int o = 16; o; o >>= 1) s += __shfl_xor_sync(0xffffffffu, s, o);
    if ((j&31)==0) r2[j>>5] = s;
    __syncthreads();
    s = r2[0]+r2[1]+r2[2]+r2[3];
    float p = e/s;
    size_t o0 = ((((size_t)0*Bq+z)*Hq+c)*Lq+i)*Lq + j;
    size_t o1 = ((((size_t)1*Bq+z)*Hq+c)*Lq+i)*Lq + j;
    g_Hm[o0] = (j > i) ? p : 0.f;
    g_Hm[o1] = (j < i) ? p : 0.f;
}

// fused per-row: G partial reduce + flash combine + compose unary + Z-softmax
__global__ void k_fuse_row(const int* __restrict__ mask, const float* __restrict__ x,
                           const int* __restrict__ m_mask, int mode){
    int row = blockIdx.x, d = threadIdx.x;
    __shared__ float ss[NSPLIT];
    __shared__ float r1[4], r2[4];

    float Gv = 0.f;
    #pragma unroll 8
    for (int p = 0; p < GPARTS; p++) Gv += g_Gpart[((size_t)p*NROWS + row)*Dq + d];

    float u;
    if (mode){
        if (d < NSPLIT) ss[d] = g_srow[d*NROWS + row];
        __syncthreads();
        float S = 0.f, Uv = 0.f;
        #pragma unroll 10
        for (int sp = 0; sp < NSPLIT; sp++){
            S  += ss[sp];
            Uv += g_Um[((size_t)sp*NROWS + row)*Dq + d];
        }
        u = Uv / S;
    } else {
        u = g_meanE[d];
    }
    float mm = (float)m_mask[row];
    float v = x[row*Dq + d]*(1.f - mm) + u*mm + Gv;

    float m = v;
    #pragma unroll
    for (int o = 16; o; o >>= 1) m = fmaxf(m, __shfl_xor_sync(0xffffffffu, m, o));
    if ((d&31)==0) r1[d>>5] = m;
    __syncthreads();
    m = fmaxf(fmaxf(r1[0],r1[1]), fmaxf(r1[2],r1[3]));
    float e = __expf(v - m);
    float s = e;
    #pragma unroll
    for (int o = 16; o; o >>= 1) s += __shfl_xor_sync(0xffffffffu, s, o);
    if ((d&31)==0) r2[d>>5] = s;
    __syncthreads();
    s = r2[0]+r2[1]+r2[2]+r2[3];
    float keep = (mask[row] != 0) ? 1.f : 0.f;
    g_qz[row*Dq + d] = e/s*keep;
}

// ---------------- fused flash V kernel (no-max exp: |logits| <= ~5.5) ----------------
#define QZW (64*132)
#define EW  (64*132)
#define PW  (64*68)
#define FLASH_SMEM ((QZW + EW + PW + 128)*4)

__global__ void __launch_bounds__(256) k_flash(const float* __restrict__ E){
    extern __shared__ uint32_t sh[];
    uint32_t* qz_s = sh;
    uint32_t* E_s  = sh + QZW;
    uint32_t* p_s  = E_s + EW;
    float* wred = (float*)(p_s + PW);  // [2][64]

    int tid = threadIdx.x;
    int sp = blockIdx.x, by = blockIdx.y;
    int warp = tid>>5, lane = tid&31;
    int wm = warp&3, wn = warp>>2;
    int g = lane>>2, q = lane&3;

    {
        const float* A = &g_qz[(by*64)*Dq];
        #pragma unroll
        for (int it = 0; it < 8; it++){
            int i4 = tid + it*256;
            int r = i4 >> 5, c4 = (i4 & 31)*4;
            float4 v = *(const float4*)&A[r*Dq + c4];
            qz_s[r*132+c4+0]=f2tf(v.x); qz_s[r*132+c4+1]=f2tf(v.y);
            qz_s[r*132+c4+2]=f2tf(v.z); qz_s[r*132+c4+3]=f2tf(v.w);
        }
    }

    float Ua[8][4];
    #pragma unroll
    for (int i = 0; i < 8; i++){ Ua[i][0]=0;Ua[i][1]=0;Ua[i][2]=0;Ua[i][3]=0; }
    float slo = 0.f, shi = 0.f;

    int v0 = sp*VCHUNK;
    int rlo = wm*16 + g, rhi = rlo + 8;

    for (int ci = 0; ci < VCHUNK/64; ci++){
        __syncthreads();   // prior MMA2 done with E_s / p_s
        const float* Eb = &E[(size_t)(v0 + ci*64)*Dq];
        #pragma unroll
        for (int it = 0; it < 8; it++){
            int i4 = tid + it*256;
            int r = i4 >> 5, c4 = (i4 & 31)*4;
            float4 v = *(const float4*)&Eb[r*Dq + c4];
            E_s[r*132+c4+0]=f2tf(v.x); E_s[r*132+c4+1]=f2tf(v.y);
            E_s[r*132+c4+2]=f2tf(v.z); E_s[r*132+c4+3]=f2tf(v.w);
        }
        __syncthreads();

        // MMA1: L[64x64] = qz @ E^T   (warp tile 16x32)
        float L[4][4];
        #pragma unroll
        for (int i = 0; i < 4; i++){ L[i][0]=0;L[i][1]=0;L[i][2]=0;L[i][3]=0; }
        const uint32_t* qrow = &qz_s[rlo*132 + q];
        #pragma unroll
        for (int ks = 0; ks < 16; ks++){
            int kb = ks*8;
            uint32_t a[4];
            a[0] = qrow[kb]; a[1] = qrow[kb + 8*132];
            a[2] = qrow[kb+4]; a[3] = qrow[kb+4 + 8*132];
            #pragma unroll
            for (int nt = 0; nt < 4; nt++){
                int nc = wn*32 + nt*8 + g;
                uint32_t b[2] = { E_s[nc*132 + kb + q], E_s[nc*132 + kb + q + 4] };
                mma8(L[nt], a, b);
            }
        }

        // p = exp(L) (no max shift needed), accumulate row sums in regs
        #pragma unroll
        for (int nt = 0; nt < 4; nt++){
            int c0 = wn*32 + nt*8 + 2*q;
            float p0 = __expf(L[nt][0]), p1 = __expf(L[nt][1]);
            float p2 = __expf(L[nt][2]), p3 = __expf(L[nt][3]);
            slo += p0 + p1; shi += p2 + p3;
            p_s[rlo*68 + c0] = f2tf(p0); p_s[rlo*68 + c0 + 1] = f2tf(p1);
            p_s[rhi*68 + c0] = f2tf(p2); p_s[rhi*68 + c0 + 1] = f2tf(p3);
        }
        __syncthreads();

        // MMA2: Ua[64x128] += p @ E   (warp tile 16x64)
        #pragma unroll
        for (int ks = 0; ks < 8; ks++){
            int kb = ks*8;
            uint32_t a[4] = { p_s[rlo*68 + kb + q], p_s[rhi*68 + kb + q],
                              p_s[rlo*68 + kb + q + 4], p_s[rhi*68 + kb + q + 4] };
            #pragma unroll
            for (int nt2 = 0; nt2 < 8; nt2++){
                int na = wn*64 + nt2*8 + g;
                uint32_t b[2] = { E_s[(kb+q)*132 + na], E_s[(kb+q+4)*132 + na] };
                mma8(Ua[nt2], a, b);
            }
        }
    }

    size_t base = ((size_t)sp*NROWS + by*64);
    #pragma unroll
    for (int nt2 = 0; nt2 < 8; nt2++){
        int col = wn*64 + nt2*8 + 2*q;
        *(float2*)&g_Um[(base + rlo)*Dq + col] = make_float2(Ua[nt2][0], Ua[nt2][1]);
        *(float2*)&g_Um[(base + rhi)*Dq + col] = make_float2(Ua[nt2][2], Ua[nt2][3]);
    }
    // final row-sum reduce: over q lanes, then over wn halves
    slo += __shfl_xor_sync(0xffffffffu, slo, 1);
    slo += __shfl_xor_sync(0xffffffffu, slo, 2);
    shi += __shfl_xor_sync(0xffffffffu, shi, 1);
    shi += __shfl_xor_sync(0xffffffffu, shi, 2);
    if (q == 0){ wred[wn*64 + rlo] = slo; wred[wn*64 + rhi] = shi; }
    __syncthreads();
    if (tid < 64)
        g_srow[sp*NROWS + by*64 + tid] = wred[tid] + wred[64+tid];
}

// final logits: out[512,32000] = qz @ E^T
#define LOGIT_SMEM ((QZW + EW)*4)
__global__ void __launch_bounds__(256) k_logits(const float* __restrict__ E, float* __restrict__ out){
    extern __shared__ uint32_t sh[];
    uint32_t* qz_s = sh;
    uint32_t* E_s  = sh + QZW;
    int tid = threadIdx.x;
    int bx = blockIdx.x, by = blockIdx.y;
    int warp = tid>>5, lane = tid&31;
    int wm = warp&3, wn = warp>>2;
    int g = lane>>2, q = lane&3;
    {
        const float* A = &g_qz[(by*64)*Dq];
        const float* Eb = &E[(size_t)(bx*64)*Dq];
        #pragma unroll
        for (int it = 0; it < 8; it++){
            int i4 = tid + it*256;
            int r = i4 >> 5, c4 = (i4 & 31)*4;
            float4 v = *(const float4*)&A[r*Dq + c4];
            qz_s[r*132+c4+0]=f2tf(v.x); qz_s[r*132+c4+1]=f2tf(v.y);
            qz_s[r*132+c4+2]=f2tf(v.z); qz_s[r*132+c4+3]=f2tf(v.w);
            float4 e = *(const float4*)&Eb[r*Dq + c4];
            E_s[r*132+c4+0]=f2tf(e.x); E_s[r*132+c4+1]=f2tf(e.y);
            E_s[r*132+c4+2]=f2tf(e.z); E_s[r*132+c4+3]=f2tf(e.w);
        }
    }
    __syncthreads();
    int rlo = wm*16 + g, rhi = rlo + 8;
    float L[4][4];
    #pragma unroll
    for (int i = 0; i < 4; i++){ L[i][0]=0;L[i][1]=0;L[i][2]=0;L[i][3]=0; }
    const uint32_t* qrow = &qz_s[rlo*132 + q];
    #pragma unroll
    for (int ks = 0; ks < 16; ks++){
        int kb = ks*8;
        uint32_t a[4];
        a[0] = qrow[kb]; a[1] = qrow[kb + 8*132];
        a[2] = qrow[kb+4]; a[3] = qrow[kb+4 + 8*132];
        #pragma unroll
        for (int nt = 0; nt < 4; nt++){
            int nc = wn*32 + nt*8 + g;
            uint32_t b[2] = { E_s[nc*132 + kb + q], E_s[nc*132 + kb + q + 4] };
            mma8(L[nt], a, b);
        }
    }
    #pragma unroll
    for (int nt = 0; nt < 4; nt++){
        int col = bx*64 + wn*32 + nt*8 + 2*q;
        *(float2*)&out[(size_t)(by*64 + rlo)*Vq + col] = make_float2(L[nt][0], L[nt][1]);
        *(float2*)&out[(size_t)(by*64 + rhi)*Vq + col] = make_float2(L[nt][2], L[nt][3]);
    }
}

// ---------------- generic strided batched tf32 GEMM, K=128 fixed ----------------
// Full-K staging: A 64x128 + B 128x64 in dynamic smem, single sync, 16 MMA steps.
#define GEMM_SMEM ((64*132 + 128*68)*4)
__global__ void __launch_bounds__(256) k_gemm_tf(
    const float* __restrict__ A, const float* __restrict__ Bm, float* __restrict__ C,
    int sAi, int sAk, int sBk, int sBj, int sCi, int sCj,
    int b3, int b2,
    int aB1, int aB2, int aB3,
    int bB1, int bB2, int bB3,
    int cB1, int cB2, int cB3,
    int aKfast, int bKfast)
{
    extern __shared__ uint32_t dsh[];
    uint32_t* As = dsh;            // [64][132]  (m-major, stride 132)
    uint32_t* Bs = dsh + 64*132;   // [128][68]  (k-major, stride 68)

    int bz = blockIdx.z;
    int i3 = bz % b3; int t_ = bz / b3; int i2 = t_ % b2; int i1 = t_ / b2;
    A  += (size_t)i1*aB1 + (size_t)i2*aB2 + (size_t)i3*aB3;
    Bm += (size_t)i1*bB1 + (size_t)i2*bB2 + (size_t)i3*bB3;
    C  += (size_t)i1*cB1 + (size_t)i2*cB2 + (size_t)i3*cB3;
    int m0 = blockIdx.y*64, n0 = blockIdx.x*64;

    int tid = threadIdx.x;
    int warp = tid>>5, lane = tid&31;
    int wm = warp&3, wn = warp>>2;
    int g = lane>>2, q = lane&3;

    // stage A (8192 elems, 32/thread)
    if (aKfast){
        #pragma unroll
        for (int p_ = 0; p_ < 32; p_++){
            int idx = tid + p_*256;
            int kk = idx & 127, mn = idx >> 7;
            As[mn*132 + kk] = f2tf(A[(size_t)(m0+mn)*sAi + (size_t)kk*sAk]);
        }
    } else {
        #pragma unroll
        for (int p_ = 0; p_ < 32; p_++){
            int idx = tid + p_*256;
            int mn = idx & 63, kk = idx >> 6;
            As[mn*132 + kk] = f2tf(A[(size_t)(m0+mn)*sAi + (size_t)kk*sAk]);
        }
    }
    // stage B (8192 elems)
    if (bKfast){
        #pragma unroll
        for (int p_ = 0; p_ < 32; p_++){
            int idx = tid + p_*256;
            int kk = idx & 127, mn = idx >> 7;
            Bs[kk*68 + mn] = f2tf(Bm[(size_t)kk*sBk + (size_t)(n0+mn)*sBj]);
        }
    } else {
        #pragma unroll
        for (int p_ = 0; p_ < 32; p_++){
            int idx = tid + p_*256;
            int mn = idx & 63, kk = idx >> 6;
            Bs[kk*68 + mn] = f2tf(Bm[(size_t)kk*sBk + (size_t)(n0+mn)*sBj]);
        }
    }
    __syncthreads();

    float acc[4][4];
    #pragma unroll
    for (int i = 0; i < 4; i++){ acc[i][0]=0;acc[i][1]=0;acc[i][2]=0;acc[i][3]=0; }

    const uint32_t* ap0 = &As[(wm*16+g)*132 + q];
    #pragma unroll
    for (int ks = 0; ks < 16; ks++){
        int kb = ks*8;
        uint32_t a[4] = { ap0[kb], ap0[kb + 8*132], ap0[kb+4], ap0[kb+4 + 8*132] };
        #pragma unroll
        for (int nt = 0; nt < 4; nt++){
            int n = wn*32 + nt*8 + g;
            uint32_t b[2] = { Bs[(kb+q)*68 + n], Bs[(kb+q+4)*68 + n] };
            mma8(acc[nt], a, b);
        }
    }

    int rlo = m0 + wm*16 + g, rhi = rlo + 8;
    #pragma unroll
    for (int nt = 0; nt < 4; nt++){
        int c0 = n0 + wn*32 + nt*8 + 2*q;
        C[(size_t)rlo*sCi + (size_t)(c0  )*sCj] = acc[nt][0];
        C[(size_t)rlo*sCi + (size_t)(c0+1)*sCj] = acc[nt][1];
        C[(size_t)rhi*sCi + (size_t)(c0  )*sCj] = acc[nt][2];
        C[(size_t)rhi*sCi + (size_t)(c0+1)*sCj] = acc[nt][3];
    }
}

// ---------------- host ----------------
extern "C" void kernel_launch(void* const* d_in, const int* in_sizes, int n_in,
                              void* d_out, int out_size){
    const float* x      = (const float*)d_in[0];
    const int*   mask   = (const int*)  d_in[1];
    const float* E      = (const float*)d_in[2];
    const int*   m_mask = (const int*)  d_in[3];
    const float* T      = (const float*)d_in[4];
    float* out = (float*)d_out;

    cudaFuncSetAttribute(k_flash,   cudaFuncAttributeMaxDynamicSharedMemorySize, FLASH_SMEM);
    cudaFuncSetAttribute(k_logits,  cudaFuncAttributeMaxDynamicSharedMemorySize, LOGIT_SMEM);
    cudaFuncSetAttribute(k_gemm_tf, cudaFuncAttributeMaxDynamicSharedMemorySize, GEMM_SMEM);

    void* qp;
    float *Pqz,*Pt1,*PF,*PHm,*Ps1,*Ps2,*PTp,*PGp;
    cudaGetSymbolAddress(&qp, g_qz);    Pqz = (float*)qp;
    cudaGetSymbolAddress(&qp, g_t1);    Pt1 = (float*)qp;
    cudaGetSymbolAddress(&qp, g_F);     PF  = (float*)qp;
    cudaGetSymbolAddress(&qp, g_Hm);    PHm = (float*)qp;
    cudaGetSymbolAddress(&qp, g_s1);    Ps1 = (float*)qp;
    cudaGetSymbolAddress(&qp, g_s2);    Ps2 = (float*)qp;
    cudaGetSymbolAddress(&qp, g_Tp);    PTp = (float*)qp;
    cudaGetSymbolAddress(&qp, g_Gpart); PGp = (float*)qp;

    // preprocessing
    k_meanE_part<<<128,128>>>(E);
    k_meanE_red<<<1,128>>>();
    k_permT<<<(2*Dq*Dq*Hq + 255)/256, 256>>>(T);
    k_compose_init<<<NROWS*Dq/256, 256>>>(x, m_mask);
    k_softmax128<<<NROWS, 128>>>(mask);

    for (int t = 0; t < 4; t++){
        // t1[z,k,i,(b,c)] = sum_a qz[z,i,a] T[k,a,(b,c)]
        k_gemm_tf<<<dim3(16,2,8), 256, GEMM_SMEM>>>(Pqz, T, Pt1,
            Dq,1,  DHq,1,  DHq,1,
            1,2,
            Lq*Dq,0,0,   0,Dq*DHq,0,   2*Lq*DHq,Lq*DHq,0,
            1,0);

        // F[z,k,c,i,j] = sum_b t1[z,k,i,(b,c)] qz[z,j,b]
        k_gemm_tf<<<dim3(2,2,64), 256, GEMM_SMEM>>>(Pt1, Pqz, PF,
            DHq,Hq,  1,Dq,  Lq,1,
            8,2,
            2*Lq*DHq,Lq*DHq,1,  Lq*Dq,0,0,  2*Hq*Lq*Lq,Hq*Lq*Lq,Lq*Lq,
            1,1);

        k_hsoftmax<<<Bq*Hq*Lq, 128>>>(mask);

        // s1[z,k,i,(b,c)] = sum_j Hm[k,z,c,i,j] qz[z,j,b]
        k_gemm_tf<<<dim3(2,2,64), 256, GEMM_SMEM>>>(PHm, Pqz, Ps1,
            Lq,1,  Dq,1,  DHq,Hq,
            8,2,
            Hq*Lq*Lq, Bq*Hq*Lq*Lq, Lq*Lq,   Lq*Dq,0,0,   2*Lq*DHq,Lq*DHq,1,
            1,0);

        // s2[z,k,j,(a,c)] = sum_i Hm[k,z,c,i,j] qz[z,i,a]
        k_gemm_tf<<<dim3(2,2,64), 256, GEMM_SMEM>>>(PHm, Pqz, Ps2,
            1,Lq,  Dq,1,  DHq,Hq,
            8,2,
            Hq*Lq*Lq, Bq*Hq*Lq*Lq, Lq*Lq,   Lq*Dq,0,0,   2*Lq*DHq,Lq*DHq,1,
            0,0);

        // G term 1 (split-K over m-chunks of 128): parts[(k*8+sk)][z,i,a]
        k_gemm_tf<<<dim3(2,2,64), 256, GEMM_SMEM>>>(Ps1, T, PGp,
            DHq,1,  1,DHq,  Dq,1,
            8,2,
            2*Lq*DHq, Lq*DHq, 128,
            0,        Dq*DHq, 128,
            Lq*Dq,    8*NROWS*Dq, NROWS*Dq,
            1,1);

        // G term 2 (split-K): parts[16 + k*8+sk][z,j,b]
        k_gemm_tf<<<dim3(2,2,64), 256, GEMM_SMEM>>>(Ps2, PTp, PGp + (size_t)16*NROWS*Dq,
            DHq,1,  Dq,1,  Dq,1,
            8,2,
            2*Lq*DHq, Lq*DHq, 128,
            0,        DHq*Dq, 128*Dq,
            Lq*Dq,    8*NROWS*Dq, NROWS*Dq,
            1,0);

        if (t > 0){
            k_flash<<<dim3(NSPLIT, 8), 256, FLASH_SMEM>>>(E);
        }
        k_fuse_row<<<NROWS, 128>>>(mask, x, m_mask, (t > 0) ? 1 : 0);

        if (t == 3){
            k_logits<<<dim3(Vq/64, 8), 256, LOGIT_SMEM>>>(E, out);
        }
    }
}